// round 1
// baseline (speedup 1.0000x reference)
#include <cuda_runtime.h>
#include <cstdint>

// ---------------------------------------------------------------------------
// LSTMRepresentationModel: 2-layer fused persistent LSTM + MLP head + LN
// B=512, T=1024, I=32, H=64, gates=256 (i,f,g,o)
// ---------------------------------------------------------------------------

#define NB    4      // batch rows per CTA
#define CTAS  128    // 128 * 4 = 512 batch rows
#define TPB   256    // one thread per gate row
#define T_LEN 1024
#define CH    16     // x chunk (timesteps buffered in smem)

typedef unsigned long long ull;

// final h of layer 2, handed from lstm kernel to head kernel
static __device__ float g_h2[512 * 64];

struct __align__(16) SM {
    float2 whh1[32 * 256];   // [k/2][j] pairs along k     64 KB
    float2 wih2[32 * 256];   //                            64 KB
    float2 whh2[32 * 256];   //                            64 KB
    float  bias1[256];       // b_ih1 + b_hh1
    float  bias2[256];
    float  h1s[64 * 4];      // [k][b]
    float  h2s[64 * 4];      // [k][b]
    float  ga1[4 * 256];     // activated gates, [b][j]
    float  ga2[4 * 256];
    float  xbuf[CH * 32 * 4];// [tl][k][b]
};

__device__ __forceinline__ ull pk2(float x, float y) {
    ull r; asm("mov.b64 %0, {%1, %2};" : "=l"(r) : "f"(x), "f"(y)); return r;
}
__device__ __forceinline__ void upk2(ull v, float& x, float& y) {
    asm("mov.b64 {%0, %1}, %2;" : "=f"(x), "=f"(y) : "l"(v));
}
__device__ __forceinline__ ull fma2(ull a, ull b, ull c) {
    ull d; asm("fma.rn.f32x2 %0, %1, %2, %3;" : "=l"(d) : "l"(a), "l"(b), "l"(c)); return d;
}

// accurate-enough sigmoid: 1/(1+2^(-x*log2e)); err ~1e-7
__device__ __forceinline__ float sigm(float x) {
    float e; asm("ex2.approx.f32 %0, %1;" : "=f"(e) : "f"(-1.4426950408889634f * x));
    float r; asm("rcp.approx.f32 %0, %1;" : "=f"(r) : "f"(1.0f + e));
    return r;
}
__device__ __forceinline__ float tanh_(float x) {
    return fmaf(2.0f, sigm(2.0f * x), -1.0f);
}

// accumulate  acc[b] += sum_k ins[k][b] * w[k][j]   for 2M k-values
template <int M>
__device__ __forceinline__ void dotseg(const float2* __restrict__ w,
                                       const float* __restrict__ ins,
                                       int j, ull& A, ull& B) {
#pragma unroll
    for (int m = 0; m < M; m++) {
        float2 wp = w[m * 256 + j];                 // LDS.64, conflict-free
        ull W0 = pk2(wp.x, wp.x);
        ull W1 = pk2(wp.y, wp.y);
        const ulonglong2* p = (const ulonglong2*)(ins + m * 8);
        ulonglong2 q0 = p[0];                       // k=2m:   {b0,b1},{b2,b3}
        ulonglong2 q1 = p[1];                       // k=2m+1
        A = fma2(q0.x, W0, A); B = fma2(q0.y, W0, B);
        A = fma2(q1.x, W1, A); B = fma2(q1.y, W1, B);
    }
}

__device__ __forceinline__ void act_store(float* __restrict__ ga, int j, ull A, ull B) {
    float v0, v1, v2, v3;
    upk2(A, v0, v1); upk2(B, v2, v3);
    if ((j >> 6) == 2) {           // g gate -> tanh  (uniform per warp)
        v0 = tanh_(v0); v1 = tanh_(v1); v2 = tanh_(v2); v3 = tanh_(v3);
    } else {                       // i,f,o -> sigmoid
        v0 = sigm(v0); v1 = sigm(v1); v2 = sigm(v2); v3 = sigm(v3);
    }
    ga[0 * 256 + j] = v0; ga[1 * 256 + j] = v1;
    ga[2 * 256 + j] = v2; ga[3 * 256 + j] = v3;
}

__global__ void __launch_bounds__(TPB, 1)
lstm_kernel(const float* __restrict__ x,
            const float* __restrict__ w_ih1, const float* __restrict__ w_hh1,
            const float* __restrict__ b_ih1, const float* __restrict__ b_hh1,
            const float* __restrict__ w_ih2, const float* __restrict__ w_hh2,
            const float* __restrict__ b_ih2, const float* __restrict__ b_hh2) {
    extern __shared__ char smraw[];
    SM& s = *reinterpret_cast<SM*>(smraw);

    const int tid = threadIdx.x;
    const int j   = tid;                 // gate row owned by this thread
    const int b0  = blockIdx.x * NB;

    // ---- load weights (transposed, k-paired) ----
    for (int i = tid; i < 256 * 64; i += TPB) {
        int jj = i >> 6, k = i & 63;
        int dst = (k >> 1) * 256 + jj;
        ((float*)&s.whh1[dst])[k & 1] = w_hh1[i];
        ((float*)&s.wih2[dst])[k & 1] = w_ih2[i];
        ((float*)&s.whh2[dst])[k & 1] = w_hh2[i];
    }
    s.bias1[tid] = b_ih1[tid] + b_hh1[tid];
    s.bias2[tid] = b_ih2[tid] + b_hh2[tid];
    s.h1s[tid] = 0.0f;                  // 256 == 64*4
    s.h2s[tid] = 0.0f;

    // w_ih1 row in registers
    float wx[32];
#pragma unroll
    for (int k = 0; k < 32; k++) wx[k] = w_ih1[j * 32 + k];

    float c1 = 0.0f, c2 = 0.0f;
    const int ub = tid >> 6;            // batch row for the elementwise update
    const int un = tid & 63;            // hidden unit
    __syncthreads();

    for (int t = 0; t < T_LEN; t++) {
        const int tl = t & (CH - 1);
        if (tl == 0) {
            // stage next CH timesteps of x into smem, layout [tl][k][b]
            for (int idx = tid; idx < CH * 32 * NB; idx += TPB) {
                int bb = idx >> 9;          // CH*32 = 512 per batch row
                int r  = idx & 511;
                int tt = r >> 5;
                int k  = r & 31;
                s.xbuf[(tt * 32 + k) * 4 + bb] =
                    x[((size_t)(b0 + bb) * T_LEN + (t + tt)) * 32 + k];
            }
            __syncthreads();
        }

        // ---- layer 1 gates ----
        {
            float bb = s.bias1[j];
            ull A = pk2(bb, bb), B = A;
            const float* xs = &s.xbuf[tl * 128];
#pragma unroll
            for (int m = 0; m < 16; m++) {          // x part, weights in regs
                ull W0 = pk2(wx[2 * m],     wx[2 * m]);
                ull W1 = pk2(wx[2 * m + 1], wx[2 * m + 1]);
                const ulonglong2* p = (const ulonglong2*)(xs + m * 8);
                ulonglong2 q0 = p[0], q1 = p[1];
                A = fma2(q0.x, W0, A); B = fma2(q0.y, W0, B);
                A = fma2(q1.x, W1, A); B = fma2(q1.y, W1, B);
            }
            dotseg<32>(s.whh1, s.h1s, j, A, B);     // h1 recurrence
            act_store(s.ga1, j, A, B);
        }
        __syncthreads();                            // ga1 ready

        // ---- layer 1 elementwise update ----
        {
            float i_ = s.ga1[ub * 256 + un];
            float f_ = s.ga1[ub * 256 + un + 64];
            float g_ = s.ga1[ub * 256 + un + 128];
            float o_ = s.ga1[ub * 256 + un + 192];
            c1 = fmaf(f_, c1, i_ * g_);
            s.h1s[un * 4 + ub] = o_ * tanh_(c1);
        }
        __syncthreads();                            // new h1 ready

        // ---- layer 2 gates ----
        {
            float bb = s.bias2[j];
            ull A = pk2(bb, bb), B = A;
            dotseg<32>(s.wih2, s.h1s, j, A, B);     // input = new h1
            dotseg<32>(s.whh2, s.h2s, j, A, B);     // h2 recurrence
            act_store(s.ga2, j, A, B);
        }
        __syncthreads();                            // ga2 ready

        // ---- layer 2 elementwise update ----
        {
            float i_ = s.ga2[ub * 256 + un];
            float f_ = s.ga2[ub * 256 + un + 64];
            float g_ = s.ga2[ub * 256 + un + 128];
            float o_ = s.ga2[ub * 256 + un + 192];
            c2 = fmaf(f_, c2, i_ * g_);
            float h = o_ * tanh_(c2);
            s.h2s[un * 4 + ub] = h;
            if (t == T_LEN - 1)
                g_h2[(size_t)(b0 + ub) * 64 + un] = h;
        }
        // no barrier needed here: next-iter readers of h2s/ga2 are separated
        // by the two barriers at the top of the next step.
    }
}

// ---- head: y = LN(relu(h@fc1^T+b1)@fc2^T+b2) ----
__global__ void __launch_bounds__(128)
head_kernel(const float* __restrict__ fc1_w, const float* __restrict__ fc1_b,
            const float* __restrict__ fc2_w, const float* __restrict__ fc2_b,
            const float* __restrict__ ln_g,  const float* __restrict__ ln_b,
            float* __restrict__ out) {
    __shared__ float h[64];
    __shared__ float y1[128];
    __shared__ float ssum[4], ssq[4];

    const int b = blockIdx.x, tid = threadIdx.x;
    if (tid < 64) h[tid] = g_h2[b * 64 + tid];
    __syncthreads();

    float a = fc1_b[tid];
#pragma unroll
    for (int k = 0; k < 64; k++) a = fmaf(h[k], fc1_w[tid * 64 + k], a);
    y1[tid] = fmaxf(a, 0.0f);
    __syncthreads();

    float a2 = fc2_b[tid];
#pragma unroll
    for (int k = 0; k < 128; k++) a2 = fmaf(y1[k], fc2_w[tid * 128 + k], a2);

    float sv = a2, sq = a2 * a2;
#pragma unroll
    for (int o = 16; o > 0; o >>= 1) {
        sv += __shfl_xor_sync(0xffffffffu, sv, o);
        sq += __shfl_xor_sync(0xffffffffu, sq, o);
    }
    if ((tid & 31) == 0) { ssum[tid >> 5] = sv; ssq[tid >> 5] = sq; }
    __syncthreads();

    float S = ssum[0] + ssum[1] + ssum[2] + ssum[3];
    float Q = ssq[0] + ssq[1] + ssq[2] + ssq[3];
    float mu  = S * (1.0f / 128.0f);
    float var = Q * (1.0f / 128.0f) - mu * mu;
    out[b * 128 + tid] = (a2 - mu) * rsqrtf(var + 1e-5f) * ln_g[tid] + ln_b[tid];
}

extern "C" void kernel_launch(void* const* d_in, const int* in_sizes, int n_in,
                              void* d_out, int out_size) {
    const float* x     = (const float*)d_in[0];
    const float* w_ih1 = (const float*)d_in[1];
    const float* w_hh1 = (const float*)d_in[2];
    const float* b_ih1 = (const float*)d_in[3];
    const float* b_hh1 = (const float*)d_in[4];
    const float* w_ih2 = (const float*)d_in[5];
    const float* w_hh2 = (const float*)d_in[6];
    const float* b_ih2 = (const float*)d_in[7];
    const float* b_hh2 = (const float*)d_in[8];
    const float* fc1_w = (const float*)d_in[9];
    const float* fc1_b = (const float*)d_in[10];
    const float* fc2_w = (const float*)d_in[11];
    const float* fc2_b = (const float*)d_in[12];
    const float* ln_g  = (const float*)d_in[13];
    const float* ln_b  = (const float*)d_in[14];
    float* out = (float*)d_out;

    cudaFuncSetAttribute(lstm_kernel,
                         cudaFuncAttributeMaxDynamicSharedMemorySize,
                         (int)sizeof(SM));
    lstm_kernel<<<CTAS, TPB, sizeof(SM)>>>(x, w_ih1, w_hh1, b_ih1, b_hh1,
                                           w_ih2, w_hh2, b_ih2, b_hh2);
    head_kernel<<<512, 128>>>(fc1_w, fc1_b, fc2_w, fc2_b, ln_g, ln_b, out);
}

// round 2
// speedup vs baseline: 1.1206x; 1.1206x over previous
#include <cuda_runtime.h>
#include <cstdint>

// ---------------------------------------------------------------------------
// 2-layer fused persistent LSTM (B=512, T=1024, I=32, H=64) + MLP head + LN
// R2: k-packed f32x2 accumulation (no pack movs), layer-1 weights in regs,
//     layer-2 weights in smem, register x-prefetch, conflict-free head.
// ---------------------------------------------------------------------------

#define NB    4      // batch rows per CTA
#define CTAS  128    // 128 * 4 = 512
#define TPB   256    // one thread per gate row
#define T_LEN 1024
#define CH    16     // x timesteps per smem chunk

typedef unsigned long long ull;

static __device__ float g_h2[512 * 64];   // final h of layer 2

struct __align__(16) SM {
    float4 wih2[16 * 256];    // [k/4][j]  64 KB
    float4 whh2[16 * 256];    // [k/4][j]  64 KB
    float  h1s[NB * 64];      // [b][k]
    float  h2s[NB * 64];      // [b][k]
    float  ga1[NB * 256];     // [b][j]
    float  ga2[NB * 256];     // [b][j]
    float  xbuf[CH * NB * 32];// [tl][b][k]
};

__device__ __forceinline__ ull pk2(float x, float y) {
    ull r; asm("mov.b64 %0, {%1, %2};" : "=l"(r) : "f"(x), "f"(y)); return r;
}
__device__ __forceinline__ void upk2(ull v, float& x, float& y) {
    asm("mov.b64 {%0, %1}, %2;" : "=f"(x), "=f"(y) : "l"(v));
}
__device__ __forceinline__ ull fma2(ull a, ull b, ull c) {
    ull d; asm("fma.rn.f32x2 %0, %1, %2, %3;" : "=l"(d) : "l"(a), "l"(b), "l"(c)); return d;
}

// sigmoid via ex2+rcp (err ~1e-7)
__device__ __forceinline__ float sigm(float x) {
    float e; asm("ex2.approx.f32 %0, %1;" : "=f"(e) : "f"(-1.4426950408889634f * x));
    float r; asm("rcp.approx.f32 %0, %1;" : "=f"(r) : "f"(1.0f + e));
    return r;
}
__device__ __forceinline__ float tanh_(float x) {
    return fmaf(2.0f, sigm(2.0f * x), -1.0f);
}

__global__ void __launch_bounds__(TPB, 1)
lstm_kernel(const float* __restrict__ x,
            const float* __restrict__ w_ih1, const float* __restrict__ w_hh1,
            const float* __restrict__ b_ih1, const float* __restrict__ b_hh1,
            const float* __restrict__ w_ih2, const float* __restrict__ w_hh2,
            const float* __restrict__ b_ih2, const float* __restrict__ b_hh2) {
    extern __shared__ char smraw[];
    SM& s = *reinterpret_cast<SM*>(smraw);

    const int tid = threadIdx.x;
    const int j   = tid;
    const int b0  = blockIdx.x * NB;

    // ---- stage layer-2 weights into smem: float4 [k/4][j] ----
    for (int i = tid; i < 256 * 64; i += TPB) {
        int jj = i >> 6, k = i & 63;
        int d = ((k >> 2) * 256 + jj) * 4 + (k & 3);
        ((float*)s.wih2)[d] = w_ih2[i];
        ((float*)s.whh2)[d] = w_hh2[i];
    }
    s.h1s[tid] = 0.0f;     // 256 == NB*64
    s.h2s[tid] = 0.0f;

    // ---- layer-1 weights in registers, k-pair packed ----
    ull wxp[16], whh1p[32];
    {
        const float2* p = (const float2*)(w_ih1 + j * 32);
#pragma unroll
        for (int g = 0; g < 16; g++) { float2 w = p[g]; wxp[g] = pk2(w.x, w.y); }
        const float2* q = (const float2*)(w_hh1 + j * 64);
#pragma unroll
        for (int g = 0; g < 32; g++) { float2 w = q[g]; whh1p[g] = pk2(w.x, w.y); }
    }
    const float myb1 = b_ih1[j] + b_hh1[j];
    const float myb2 = b_ih2[j] + b_hh2[j];

    // ---- x chunk staging indices (8 consecutive floats per thread) ----
    const int i0  = tid * 8;
    const int pbb = i0 >> 9;          // CH*32 = 512 floats per batch row
    const int pr  = i0 & 511;
    const int ptl = pr >> 5;
    const int pk  = pr & 31;
    const float* xsrc = x + ((size_t)(b0 + pbb) * T_LEN + ptl) * 32 + pk;
    float*       xdst = s.xbuf + (ptl * NB + pbb) * 32 + pk;

    // chunk 0 directly to smem; prefetch chunk 1 into regs
    float4 xf0 = *(const float4*)(xsrc);
    float4 xf1 = *(const float4*)(xsrc + 4);
    *(float4*)xdst       = xf0;
    *(float4*)(xdst + 4) = xf1;
    xf0 = *(const float4*)(xsrc + CH * 32);
    xf1 = *(const float4*)(xsrc + CH * 32 + 4);

    float c1 = 0.0f, c2 = 0.0f;
    const int ub = tid >> 6;          // batch row for elementwise update
    const int un = tid & 63;          // hidden unit
    const bool is_g_gate = ((j >> 6) == 2);   // warp-uniform
    __syncthreads();

    for (int t = 0; t < T_LEN; t++) {
        const int tl = t & (CH - 1);
        if (tl == 0 && t) {
            // prev chunk readers are all past the last barrier (reads precede it)
            *(float4*)xdst       = xf0;
            *(float4*)(xdst + 4) = xf1;
            __syncthreads();
            if (t + CH < T_LEN) {
                const float* src = xsrc + (size_t)(t + CH) * 32;
                xf0 = *(const float4*)src;
                xf1 = *(const float4*)(src + 4);
            }
        }

        // ================= layer 1 gates =================
        ull a0 = pk2(myb1, 0.0f), a1 = a0, a2 = a0, a3 = a0;
        {
            const float* xb = s.xbuf + tl * (NB * 32);
#pragma unroll
            for (int g = 0; g < 8; g++) {              // x part (weights in regs)
                ulonglong2 v0 = *(const ulonglong2*)(xb +  0 + g * 4);
                ulonglong2 v1 = *(const ulonglong2*)(xb + 32 + g * 4);
                ulonglong2 v2 = *(const ulonglong2*)(xb + 64 + g * 4);
                ulonglong2 v3 = *(const ulonglong2*)(xb + 96 + g * 4);
                a0 = fma2(v0.x, wxp[2*g], a0); a0 = fma2(v0.y, wxp[2*g+1], a0);
                a1 = fma2(v1.x, wxp[2*g], a1); a1 = fma2(v1.y, wxp[2*g+1], a1);
                a2 = fma2(v2.x, wxp[2*g], a2); a2 = fma2(v2.y, wxp[2*g+1], a2);
                a3 = fma2(v3.x, wxp[2*g], a3); a3 = fma2(v3.y, wxp[2*g+1], a3);
            }
#pragma unroll
            for (int g = 0; g < 16; g++) {             // h1 recurrence (weights in regs)
                ulonglong2 v0 = *(const ulonglong2*)(s.h1s +   0 + g * 4);
                ulonglong2 v1 = *(const ulonglong2*)(s.h1s +  64 + g * 4);
                ulonglong2 v2 = *(const ulonglong2*)(s.h1s + 128 + g * 4);
                ulonglong2 v3 = *(const ulonglong2*)(s.h1s + 192 + g * 4);
                a0 = fma2(v0.x, whh1p[2*g], a0); a0 = fma2(v0.y, whh1p[2*g+1], a0);
                a1 = fma2(v1.x, whh1p[2*g], a1); a1 = fma2(v1.y, whh1p[2*g+1], a1);
                a2 = fma2(v2.x, whh1p[2*g], a2); a2 = fma2(v2.y, whh1p[2*g+1], a2);
                a3 = fma2(v3.x, whh1p[2*g], a3); a3 = fma2(v3.y, whh1p[2*g+1], a3);
            }
        }
        {
            float e0, o0, e1, o1, e2, o2, e3, o3;
            upk2(a0, e0, o0); upk2(a1, e1, o1); upk2(a2, e2, o2); upk2(a3, e3, o3);
            float v0 = e0 + o0, v1 = e1 + o1, v2 = e2 + o2, v3 = e3 + o3;
            if (is_g_gate) { v0 = tanh_(v0); v1 = tanh_(v1); v2 = tanh_(v2); v3 = tanh_(v3); }
            else           { v0 = sigm(v0);  v1 = sigm(v1);  v2 = sigm(v2);  v3 = sigm(v3);  }
            s.ga1[      j] = v0; s.ga1[256 + j] = v1;
            s.ga1[512 + j] = v2; s.ga1[768 + j] = v3;
        }
        __syncthreads();

        // ================= layer 1 update =================
        {
            const float* g1 = s.ga1 + ub * 256;
            float i_ = g1[un], f_ = g1[un + 64], g_ = g1[un + 128], o_ = g1[un + 192];
            c1 = fmaf(f_, c1, i_ * g_);
            s.h1s[ub * 64 + un] = o_ * tanh_(c1);
        }
        __syncthreads();

        // ================= layer 2 gates =================
        a0 = pk2(myb2, 0.0f); a1 = a0; a2 = a0; a3 = a0;
#pragma unroll
        for (int g = 0; g < 16; g++) {                 // input = new h1, weights smem
            ulonglong2 w  = *(const ulonglong2*)&s.wih2[g * 256 + j];
            ulonglong2 v0 = *(const ulonglong2*)(s.h1s +   0 + g * 4);
            ulonglong2 v1 = *(const ulonglong2*)(s.h1s +  64 + g * 4);
            ulonglong2 v2 = *(const ulonglong2*)(s.h1s + 128 + g * 4);
            ulonglong2 v3 = *(const ulonglong2*)(s.h1s + 192 + g * 4);
            a0 = fma2(v0.x, w.x, a0); a0 = fma2(v0.y, w.y, a0);
            a1 = fma2(v1.x, w.x, a1); a1 = fma2(v1.y, w.y, a1);
            a2 = fma2(v2.x, w.x, a2); a2 = fma2(v2.y, w.y, a2);
            a3 = fma2(v3.x, w.x, a3); a3 = fma2(v3.y, w.y, a3);
        }
#pragma unroll
        for (int g = 0; g < 16; g++) {                 // h2 recurrence, weights smem
            ulonglong2 w  = *(const ulonglong2*)&s.whh2[g * 256 + j];
            ulonglong2 v0 = *(const ulonglong2*)(s.h2s +   0 + g * 4);
            ulonglong2 v1 = *(const ulonglong2*)(s.h2s +  64 + g * 4);
            ulonglong2 v2 = *(const ulonglong2*)(s.h2s + 128 + g * 4);
            ulonglong2 v3 = *(const ulonglong2*)(s.h2s + 192 + g * 4);
            a0 = fma2(v0.x, w.x, a0); a0 = fma2(v0.y, w.y, a0);
            a1 = fma2(v1.x, w.x, a1); a1 = fma2(v1.y, w.y, a1);
            a2 = fma2(v2.x, w.x, a2); a2 = fma2(v2.y, w.y, a2);
            a3 = fma2(v3.x, w.x, a3); a3 = fma2(v3.y, w.y, a3);
        }
        {
            float e0, o0, e1, o1, e2, o2, e3, o3;
            upk2(a0, e0, o0); upk2(a1, e1, o1); upk2(a2, e2, o2); upk2(a3, e3, o3);
            float v0 = e0 + o0, v1 = e1 + o1, v2 = e2 + o2, v3 = e3 + o3;
            if (is_g_gate) { v0 = tanh_(v0); v1 = tanh_(v1); v2 = tanh_(v2); v3 = tanh_(v3); }
            else           { v0 = sigm(v0);  v1 = sigm(v1);  v2 = sigm(v2);  v3 = sigm(v3);  }
            s.ga2[      j] = v0; s.ga2[256 + j] = v1;
            s.ga2[512 + j] = v2; s.ga2[768 + j] = v3;
        }
        __syncthreads();

        // ================= layer 2 update =================
        {
            const float* g2 = s.ga2 + ub * 256;
            float i_ = g2[un], f_ = g2[un + 64], g_ = g2[un + 128], o_ = g2[un + 192];
            c2 = fmaf(f_, c2, i_ * g_);
            float h = o_ * tanh_(c2);
            s.h2s[ub * 64 + un] = h;
            if (t == T_LEN - 1)
                g_h2[(size_t)(b0 + ub) * 64 + un] = h;
        }
        // no barrier: next-step readers separated by two barriers (see analysis)
    }
}

// ---------------------------------------------------------------------------
// head: y = LN(relu(h@fc1^T+b1)@fc2^T+b2); 128 blocks x 4 batches,
// weights staged in padded smem (stride 65/129 -> conflict-free).
// ---------------------------------------------------------------------------
#define HB 4

__global__ void __launch_bounds__(128)
head_kernel(const float* __restrict__ fc1_w, const float* __restrict__ fc1_b,
            const float* __restrict__ fc2_w, const float* __restrict__ fc2_b,
            const float* __restrict__ ln_g,  const float* __restrict__ ln_b,
            float* __restrict__ out) {
    extern __shared__ float hs[];
    float* w1  = hs;                   // 128*65
    float* w2  = w1 + 128 * 65;        // 128*129
    float* hv  = w2 + 128 * 129;       // HB*64
    float* y1  = hv + HB * 64;         // 128
    float* rs  = y1 + 128;             // HB*4
    float* rq  = rs + HB * 4;          // HB*4

    const int tid = threadIdx.x;
    const int b0  = blockIdx.x * HB;

    for (int i = tid; i < 8192;  i += 128) w1[(i >> 6) * 65  + (i & 63)]  = fc1_w[i];
    for (int i = tid; i < 16384; i += 128) w2[(i >> 7) * 129 + (i & 127)] = fc2_w[i];
    for (int i = tid; i < HB * 64; i += 128) hv[i] = g_h2[(size_t)b0 * 64 + i];
    const float b1v = fc1_b[tid], b2v = fc2_b[tid];
    __syncthreads();

    float a2v[HB];
#pragma unroll
    for (int bb = 0; bb < HB; bb++) {
        float s0 = b1v, s1 = 0.0f;
#pragma unroll
        for (int k = 0; k < 64; k += 2) {
            s0 = fmaf(hv[bb * 64 + k],     w1[tid * 65 + k],     s0);
            s1 = fmaf(hv[bb * 64 + k + 1], w1[tid * 65 + k + 1], s1);
        }
        y1[tid] = fmaxf(s0 + s1, 0.0f);
        __syncthreads();
        float t0 = b2v, t1 = 0.0f;
#pragma unroll
        for (int k = 0; k < 128; k += 2) {
            t0 = fmaf(y1[k],     w2[tid * 129 + k],     t0);
            t1 = fmaf(y1[k + 1], w2[tid * 129 + k + 1], t1);
        }
        a2v[bb] = t0 + t1;
        __syncthreads();                // before y1 reuse
    }

#pragma unroll
    for (int bb = 0; bb < HB; bb++) {
        float sv = a2v[bb], sq = a2v[bb] * a2v[bb];
#pragma unroll
        for (int o = 16; o > 0; o >>= 1) {
            sv += __shfl_xor_sync(0xffffffffu, sv, o);
            sq += __shfl_xor_sync(0xffffffffu, sq, o);
        }
        if ((tid & 31) == 0) { rs[bb * 4 + (tid >> 5)] = sv; rq[bb * 4 + (tid >> 5)] = sq; }
    }
    __syncthreads();

    const float gv = ln_g[tid], bv = ln_b[tid];
#pragma unroll
    for (int bb = 0; bb < HB; bb++) {
        float S = rs[bb*4] + rs[bb*4+1] + rs[bb*4+2] + rs[bb*4+3];
        float Q = rq[bb*4] + rq[bb*4+1] + rq[bb*4+2] + rq[bb*4+3];
        float mu  = S * (1.0f / 128.0f);
        float var = Q * (1.0f / 128.0f) - mu * mu;
        out[(size_t)(b0 + bb) * 128 + tid] =
            (a2v[bb] - mu) * rsqrtf(var + 1e-5f) * gv + bv;
    }
}

extern "C" void kernel_launch(void* const* d_in, const int* in_sizes, int n_in,
                              void* d_out, int out_size) {
    const float* x     = (const float*)d_in[0];
    const float* w_ih1 = (const float*)d_in[1];
    const float* w_hh1 = (const float*)d_in[2];
    const float* b_ih1 = (const float*)d_in[3];
    const float* b_hh1 = (const float*)d_in[4];
    const float* w_ih2 = (const float*)d_in[5];
    const float* w_hh2 = (const float*)d_in[6];
    const float* b_ih2 = (const float*)d_in[7];
    const float* b_hh2 = (const float*)d_in[8];
    const float* fc1_w = (const float*)d_in[9];
    const float* fc1_b = (const float*)d_in[10];
    const float* fc2_w = (const float*)d_in[11];
    const float* fc2_b = (const float*)d_in[12];
    const float* ln_g  = (const float*)d_in[13];
    const float* ln_b  = (const float*)d_in[14];
    float* out = (float*)d_out;

    cudaFuncSetAttribute(lstm_kernel,
                         cudaFuncAttributeMaxDynamicSharedMemorySize,
                         (int)sizeof(SM));
    lstm_kernel<<<CTAS, TPB, sizeof(SM)>>>(x, w_ih1, w_hh1, b_ih1, b_hh1,
                                           w_ih2, w_hh2, b_ih2, b_hh2);

    int head_smem = (128 * 65 + 128 * 129 + HB * 64 + 128 + HB * 8) * (int)sizeof(float);
    cudaFuncSetAttribute(head_kernel,
                         cudaFuncAttributeMaxDynamicSharedMemorySize, head_smem);
    head_kernel<<<512 / HB, 128, head_smem>>>(fc1_w, fc1_b, fc2_w, fc2_b,
                                              ln_g, ln_b, out);
}

// round 3
// speedup vs baseline: 1.3804x; 1.2319x over previous
#include <cuda_runtime.h>
#include <cstdint>

// ---------------------------------------------------------------------------
// 2-layer fused persistent LSTM (B=512, T=1024, I=32, H=64) + MLP head + LN
// R3: fused cross-layer gates phase (2 barriers/step), w_ih1+w_ih2+w_hh1 layer
//     weights register/smem split to keep crossbar under the fma floor,
//     cp.async double-buffered x staging, low-overhead head.
// ---------------------------------------------------------------------------

#define NB    4
#define CTAS  128
#define TPB   256
#define T_LEN 1024
#define CH    16

typedef unsigned long long ull;

static __device__ float g_h2[512 * 64];

struct __align__(16) SM {
    float4 wih1[8 * 256];     // [k/4][j]   32 KB
    float4 whh2[16 * 256];    // [k/4][j]   64 KB
    float  h1s[256];          // [b][k]
    float  h2s[256];          // [b][k]
    float  ga1[1024];         // [b][j]
    float  ga2[1024];         // [b][j]
    float  xbuf[2 * CH * NB * 32];   // double-buffered, [buf][tl][b][k] 16 KB
};

__device__ __forceinline__ ull pk2(float x, float y) {
    ull r; asm("mov.b64 %0, {%1, %2};" : "=l"(r) : "f"(x), "f"(y)); return r;
}
__device__ __forceinline__ void upk2(ull v, float& x, float& y) {
    asm("mov.b64 {%0, %1}, %2;" : "=f"(x), "=f"(y) : "l"(v));
}
__device__ __forceinline__ ull fma2(ull a, ull b, ull c) {
    ull d; asm("fma.rn.f32x2 %0, %1, %2, %3;" : "=l"(d) : "l"(a), "l"(b), "l"(c)); return d;
}
__device__ __forceinline__ float sigm(float x) {
    float e; asm("ex2.approx.f32 %0, %1;" : "=f"(e) : "f"(-1.4426950408889634f * x));
    float r; asm("rcp.approx.f32 %0, %1;" : "=f"(r) : "f"(1.0f + e));
    return r;
}
__device__ __forceinline__ float tanh_(float x) {
    return fmaf(2.0f, sigm(2.0f * x), -1.0f);
}
__device__ __forceinline__ void cpasync16(uint32_t dst, const void* src) {
    asm volatile("cp.async.ca.shared.global [%0], [%1], 16;" :: "r"(dst), "l"(src));
}

// activate 4 packed accumulators (even/odd horizontal add) and store to ga[b][j]
__device__ __forceinline__ void act4(float* __restrict__ ga, int j, bool is_g,
                                     ull a0, ull a1, ull a2, ull a3) {
    float e0,o0,e1,o1,e2,o2,e3,o3;
    upk2(a0,e0,o0); upk2(a1,e1,o1); upk2(a2,e2,o2); upk2(a3,e3,o3);
    float v0 = e0+o0, v1 = e1+o1, v2 = e2+o2, v3 = e3+o3;
    if (is_g) { v0=tanh_(v0); v1=tanh_(v1); v2=tanh_(v2); v3=tanh_(v3); }
    else      { v0=sigm(v0);  v1=sigm(v1);  v2=sigm(v2);  v3=sigm(v3);  }
    ga[      j] = v0; ga[256 + j] = v1; ga[512 + j] = v2; ga[768 + j] = v3;
}

__global__ void __launch_bounds__(TPB, 1)
lstm_kernel(const float* __restrict__ x,
            const float* __restrict__ w_ih1, const float* __restrict__ w_hh1,
            const float* __restrict__ b_ih1, const float* __restrict__ b_hh1,
            const float* __restrict__ w_ih2, const float* __restrict__ w_hh2,
            const float* __restrict__ b_ih2, const float* __restrict__ b_hh2) {
    extern __shared__ char smraw[];
    SM& s = *reinterpret_cast<SM*>(smraw);

    const int tid = threadIdx.x;
    const int j   = tid;
    const int b0  = blockIdx.x * NB;

    // ---- stage smem weights: w_ih1 and w_hh2, layout float4 [k/4][j] ----
    for (int i = tid; i < 256 * 32; i += TPB) {
        int jj = i >> 5, k = i & 31;
        ((float*)s.wih1)[((k >> 2) * 256 + jj) * 4 + (k & 3)] = w_ih1[i];
    }
    for (int i = tid; i < 256 * 64; i += TPB) {
        int jj = i >> 6, k = i & 63;
        ((float*)s.whh2)[((k >> 2) * 256 + jj) * 4 + (k & 3)] = w_hh2[i];
    }
    s.h2s[tid] = 0.0f;    // 256 == NB*64 (h1s fully written in prologue upd1)

    // ---- register weights: w_hh1 row j and w_ih2 row j, k-pair packed ----
    ull whh1p[32], wih2p[32];
    {
        const float2* q = (const float2*)(w_hh1 + j * 64);
#pragma unroll
        for (int g = 0; g < 32; g++) { float2 w = q[g]; whh1p[g] = pk2(w.x, w.y); }
        const float2* p = (const float2*)(w_ih2 + j * 64);
#pragma unroll
        for (int g = 0; g < 32; g++) { float2 w = p[g]; wih2p[g] = pk2(w.x, w.y); }
    }
    const float myb1 = b_ih1[j] + b_hh1[j];
    const float myb2 = b_ih2[j] + b_hh2[j];

    // ---- x staging via cp.async: thread owns 8 consecutive floats ----
    const int ptl = tid >> 4;            // 0..15
    const int pbb = (tid >> 2) & 3;      // batch col
    const int pk  = (tid & 3) * 8;       // k offset
    const float* xsrc0 = x + ((size_t)(b0 + pbb) * T_LEN + ptl) * 32 + pk;
    uint32_t xbase = (uint32_t)__cvta_generic_to_shared(s.xbuf)
                   + (((ptl * NB + pbb) * 32 + pk) << 2);

#define STAGE(chunk) do {                                                    \
        const float* _src = xsrc0 + (size_t)(chunk) * (CH * 32);             \
        uint32_t _dst = xbase + (((chunk) & 1) ? (2048u << 2) : 0u);         \
        cpasync16(_dst,      _src);                                          \
        cpasync16(_dst + 16, _src + 4);                                      \
        asm volatile("cp.async.commit_group;");                              \
    } while (0)

    STAGE(0);
    STAGE(1);
    asm volatile("cp.async.wait_group 1;");   // chunk 0 resident

    float c1 = 0.0f, c2 = 0.0f;
    const int  ub = tid >> 6;
    const int  un = tid & 63;
    const bool is_g = ((j >> 6) == 2);        // warp-uniform
    __syncthreads();

    // ================= prologue: g1(0) (h0 == 0 -> x part only) ============
    {
        ull B0 = pk2(myb1, 0.0f), B1 = B0, B2 = B0, B3 = B0;
        const float* xb = s.xbuf;             // buf0, tl=0
#pragma unroll
        for (int g = 0; g < 8; g++) {
            ulonglong2 w  = *(const ulonglong2*)&s.wih1[g * 256 + j];
            ulonglong2 v0 = *(const ulonglong2*)(xb +  0 + g * 4);
            ulonglong2 v1 = *(const ulonglong2*)(xb + 32 + g * 4);
            ulonglong2 v2 = *(const ulonglong2*)(xb + 64 + g * 4);
            ulonglong2 v3 = *(const ulonglong2*)(xb + 96 + g * 4);
            B0 = fma2(v0.x, w.x, B0); B0 = fma2(v0.y, w.y, B0);
            B1 = fma2(v1.x, w.x, B1); B1 = fma2(v1.y, w.y, B1);
            B2 = fma2(v2.x, w.x, B2); B2 = fma2(v2.y, w.y, B2);
            B3 = fma2(v3.x, w.x, B3); B3 = fma2(v3.y, w.y, B3);
        }
        act4(s.ga1, j, is_g, B0, B1, B2, B3);
    }
    __syncthreads();
    {   // upd1(0)
        const float* g1 = s.ga1 + ub * 256;
        float i_ = g1[un], f_ = g1[un+64], g_ = g1[un+128], o_ = g1[un+192];
        c1 = fmaf(f_, c1, i_ * g_);
        s.h1s[ub * 64 + un] = o_ * tanh_(c1);
    }
    __syncthreads();

    // ================= main loop ==========================================
    for (int t = 0; t < T_LEN; t++) {
        const int tp1 = t + 1;
        if ((tp1 & (CH - 1)) == 0 && tp1 < T_LEN) {
            asm volatile("cp.async.wait_group 0;");
            __syncthreads();
            int cc = tp1 >> 4;
            if (cc + 1 < T_LEN / CH) STAGE(cc + 1);
        }

        // ---- fused gates: g2(t) in A*, g1(t+1) in B* ----
        ull A0 = pk2(myb2, 0.0f), A1 = A0, A2 = A0, A3 = A0;
        ull B0 = pk2(myb1, 0.0f), B1 = B0, B2 = B0, B3 = B0;

        // shared h1 broadcasts feed both wih2p (A) and whh1p (B)
#pragma unroll
        for (int g = 0; g < 16; g++) {
            ulonglong2 v0 = *(const ulonglong2*)(s.h1s +   0 + g * 4);
            ulonglong2 v1 = *(const ulonglong2*)(s.h1s +  64 + g * 4);
            ulonglong2 v2 = *(const ulonglong2*)(s.h1s + 128 + g * 4);
            ulonglong2 v3 = *(const ulonglong2*)(s.h1s + 192 + g * 4);
            A0 = fma2(v0.x, wih2p[2*g], A0); A0 = fma2(v0.y, wih2p[2*g+1], A0);
            A1 = fma2(v1.x, wih2p[2*g], A1); A1 = fma2(v1.y, wih2p[2*g+1], A1);
            A2 = fma2(v2.x, wih2p[2*g], A2); A2 = fma2(v2.y, wih2p[2*g+1], A2);
            A3 = fma2(v3.x, wih2p[2*g], A3); A3 = fma2(v3.y, wih2p[2*g+1], A3);
            B0 = fma2(v0.x, whh1p[2*g], B0); B0 = fma2(v0.y, whh1p[2*g+1], B0);
            B1 = fma2(v1.x, whh1p[2*g], B1); B1 = fma2(v1.y, whh1p[2*g+1], B1);
            B2 = fma2(v2.x, whh1p[2*g], B2); B2 = fma2(v2.y, whh1p[2*g+1], B2);
            B3 = fma2(v3.x, whh1p[2*g], B3); B3 = fma2(v3.y, whh1p[2*g+1], B3);
        }
        // g2 recurrent part: h2(t-1) with smem whh2
#pragma unroll
        for (int g = 0; g < 16; g++) {
            ulonglong2 w  = *(const ulonglong2*)&s.whh2[g * 256 + j];
            ulonglong2 v0 = *(const ulonglong2*)(s.h2s +   0 + g * 4);
            ulonglong2 v1 = *(const ulonglong2*)(s.h2s +  64 + g * 4);
            ulonglong2 v2 = *(const ulonglong2*)(s.h2s + 128 + g * 4);
            ulonglong2 v3 = *(const ulonglong2*)(s.h2s + 192 + g * 4);
            A0 = fma2(v0.x, w.x, A0); A0 = fma2(v0.y, w.y, A0);
            A1 = fma2(v1.x, w.x, A1); A1 = fma2(v1.y, w.y, A1);
            A2 = fma2(v2.x, w.x, A2); A2 = fma2(v2.y, w.y, A2);
            A3 = fma2(v3.x, w.x, A3); A3 = fma2(v3.y, w.y, A3);
        }
        // g1(t+1) x part with smem wih1 (stale data at t==T-1: B unused)
        {
            const float* xb = s.xbuf + ((tp1 >> 4) & 1) * 2048
                                     + (tp1 & (CH - 1)) * (NB * 32);
#pragma unroll
            for (int g = 0; g < 8; g++) {
                ulonglong2 w  = *(const ulonglong2*)&s.wih1[g * 256 + j];
                ulonglong2 v0 = *(const ulonglong2*)(xb +  0 + g * 4);
                ulonglong2 v1 = *(const ulonglong2*)(xb + 32 + g * 4);
                ulonglong2 v2 = *(const ulonglong2*)(xb + 64 + g * 4);
                ulonglong2 v3 = *(const ulonglong2*)(xb + 96 + g * 4);
                B0 = fma2(v0.x, w.x, B0); B0 = fma2(v0.y, w.y, B0);
                B1 = fma2(v1.x, w.x, B1); B1 = fma2(v1.y, w.y, B1);
                B2 = fma2(v2.x, w.x, B2); B2 = fma2(v2.y, w.y, B2);
                B3 = fma2(v3.x, w.x, B3); B3 = fma2(v3.y, w.y, B3);
            }
        }
        act4(s.ga2, j, is_g, A0, A1, A2, A3);
        act4(s.ga1, j, is_g, B0, B1, B2, B3);
        __syncthreads();

        // ---- fused updates: upd2(t) and upd1(t+1) ----
        {
            const float* g2 = s.ga2 + ub * 256;
            float i_ = g2[un], f_ = g2[un+64], g_ = g2[un+128], o_ = g2[un+192];
            c2 = fmaf(f_, c2, i_ * g_);
            float h = o_ * tanh_(c2);
            s.h2s[ub * 64 + un] = h;
            if (t == T_LEN - 1)
                g_h2[(size_t)(b0 + ub) * 64 + un] = h;
        }
        if (t < T_LEN - 1) {
            const float* g1 = s.ga1 + ub * 256;
            float i_ = g1[un], f_ = g1[un+64], g_ = g1[un+128], o_ = g1[un+192];
            c1 = fmaf(f_, c1, i_ * g_);
            s.h1s[ub * 64 + un] = o_ * tanh_(c1);
        }
        __syncthreads();
    }
#undef STAGE
}

// ---------------------------------------------------------------------------
// head: 32 blocks x 16 batches; padded smem weights (stride 65/129).
// ---------------------------------------------------------------------------
#define HB 16

__global__ void __launch_bounds__(128)
head_kernel(const float* __restrict__ fc1_w, const float* __restrict__ fc1_b,
            const float* __restrict__ fc2_w, const float* __restrict__ fc2_b,
            const float* __restrict__ ln_g,  const float* __restrict__ ln_b,
            float* __restrict__ out) {
    extern __shared__ float hs[];
    float* w1 = hs;                    // 128*65
    float* w2 = w1 + 128 * 65;         // 128*129
    float* hv = w2 + 128 * 129;        // HB*64
    float* y1 = hv + HB * 64;          // 128
    float* rs = y1 + 128;              // 4
    float* rq = rs + 4;                // 4

    const int tid = threadIdx.x;
    const int b0  = blockIdx.x * HB;

    for (int i = tid; i < 8192;  i += 128) w1[(i >> 6) * 65  + (i & 63)]  = fc1_w[i];
    for (int i = tid; i < 16384; i += 128) w2[(i >> 7) * 129 + (i & 127)] = fc2_w[i];
    for (int i = tid; i < HB * 64; i += 128) hv[i] = g_h2[(size_t)b0 * 64 + i];
    const float b1v = fc1_b[tid], b2v = fc2_b[tid];
    const float gv = ln_g[tid],   bv = ln_b[tid];
    __syncthreads();

    float a2v[HB];
#pragma unroll 1
    for (int bb = 0; bb < HB; bb++) {
        float s0 = b1v, s1 = 0.0f;
#pragma unroll
        for (int k = 0; k < 64; k += 2) {
            s0 = fmaf(hv[bb * 64 + k],     w1[tid * 65 + k],     s0);
            s1 = fmaf(hv[bb * 64 + k + 1], w1[tid * 65 + k + 1], s1);
        }
        y1[tid] = fmaxf(s0 + s1, 0.0f);
        __syncthreads();
        float t0 = b2v, t1 = 0.0f;
#pragma unroll
        for (int k = 0; k < 128; k += 2) {
            t0 = fmaf(y1[k],     w2[tid * 129 + k],     t0);
            t1 = fmaf(y1[k + 1], w2[tid * 129 + k + 1], t1);
        }
        a2v[bb] = t0 + t1;
        __syncthreads();
    }

#pragma unroll 1
    for (int bb = 0; bb < HB; bb++) {
        float sv = a2v[bb], sq = a2v[bb] * a2v[bb];
#pragma unroll
        for (int o = 16; o > 0; o >>= 1) {
            sv += __shfl_xor_sync(0xffffffffu, sv, o);
            sq += __shfl_xor_sync(0xffffffffu, sq, o);
        }
        if ((tid & 31) == 0) { rs[tid >> 5] = sv; rq[tid >> 5] = sq; }
        __syncthreads();
        float S = rs[0] + rs[1] + rs[2] + rs[3];
        float Q = rq[0] + rq[1] + rq[2] + rq[3];
        float mu  = S * (1.0f / 128.0f);
        float var = Q * (1.0f / 128.0f) - mu * mu;
        out[(size_t)(b0 + bb) * 128 + tid] =
            (a2v[bb] - mu) * rsqrtf(var + 1e-5f) * gv + bv;
        __syncthreads();
    }
}

extern "C" void kernel_launch(void* const* d_in, const int* in_sizes, int n_in,
                              void* d_out, int out_size) {
    const float* x     = (const float*)d_in[0];
    const float* w_ih1 = (const float*)d_in[1];
    const float* w_hh1 = (const float*)d_in[2];
    const float* b_ih1 = (const float*)d_in[3];
    const float* b_hh1 = (const float*)d_in[4];
    const float* w_ih2 = (const float*)d_in[5];
    const float* w_hh2 = (const float*)d_in[6];
    const float* b_ih2 = (const float*)d_in[7];
    const float* b_hh2 = (const float*)d_in[8];
    const float* fc1_w = (const float*)d_in[9];
    const float* fc1_b = (const float*)d_in[10];
    const float* fc2_w = (const float*)d_in[11];
    const float* fc2_b = (const float*)d_in[12];
    const float* ln_g  = (const float*)d_in[13];
    const float* ln_b  = (const float*)d_in[14];
    float* out = (float*)d_out;

    cudaFuncSetAttribute(lstm_kernel,
                         cudaFuncAttributeMaxDynamicSharedMemorySize,
                         (int)sizeof(SM));
    lstm_kernel<<<CTAS, TPB, sizeof(SM)>>>(x, w_ih1, w_hh1, b_ih1, b_hh1,
                                           w_ih2, w_hh2, b_ih2, b_hh2);

    int head_smem = (128 * 65 + 128 * 129 + HB * 64 + 128 + 8) * (int)sizeof(float);
    cudaFuncSetAttribute(head_kernel,
                         cudaFuncAttributeMaxDynamicSharedMemorySize, head_smem);
    head_kernel<<<512 / HB, 128, head_smem>>>(fc1_w, fc1_b, fc2_w, fc2_b,
                                              ln_g, ln_b, out);
}

// round 6
// speedup vs baseline: 2.6352x; 1.9089x over previous
#include <cuda_runtime.h>
#include <cuda_fp16.h>
#include <cstdint>

// R6: mma.sync m16n8k16 fp16 (f32 accum) persistent 2-layer LSTM.
// 64 CTAs x 512 thr, 8 batch/CTA. Weights = fp16 A-fragments in registers.
// Inputs split fp16 hi+lo (2-pass). Round t = {gates2(t), gates1(t+1)}.

#define CTAS  64
#define TPB   512
#define T_LEN 1024

static __device__ float g_h2[512 * 64];

__device__ __forceinline__ uint32_t pkh(float a, float b) {
    __half ha = __float2half_rn(a), hb = __float2half_rn(b);
    return (uint32_t)__half_as_ushort(ha) | ((uint32_t)__half_as_ushort(hb) << 16);
}
__device__ __forceinline__ void hsplit2(float a, float b, uint32_t& hi, uint32_t& lo) {
    __half ha = __float2half_rn(a), hb = __float2half_rn(b);
    hi = (uint32_t)__half_as_ushort(ha) | ((uint32_t)__half_as_ushort(hb) << 16);
    lo = (uint32_t)__half_as_ushort(__float2half_rn(a - __half2float(ha)))
       | ((uint32_t)__half_as_ushort(__float2half_rn(b - __half2float(hb))) << 16);
}
__device__ __forceinline__ float tanhax(float x) {
    float y; asm("tanh.approx.f32 %0,%1;" : "=f"(y) : "f"(x)); return y;
}
__device__ __forceinline__ float sigm(float x) { return fmaf(tanhax(0.5f * x), 0.5f, 0.5f); }

__device__ __forceinline__ void mma16(float* d, const uint32_t* a, uint32_t b0, uint32_t b1) {
    asm volatile(
        "mma.sync.aligned.m16n8k16.row.col.f32.f16.f16.f32 "
        "{%0,%1,%2,%3},{%4,%5,%6,%7},{%8,%9},{%0,%1,%2,%3};"
        : "+f"(d[0]), "+f"(d[1]), "+f"(d[2]), "+f"(d[3])
        : "r"(a[0]), "r"(a[1]), "r"(a[2]), "r"(a[3]), "r"(b0), "r"(b1));
}
__device__ __forceinline__ void cpa16(uint32_t d, const void* s) {
    asm volatile("cp.async.ca.shared.global [%0],[%1],16;" :: "r"(d), "l"(s));
}
__device__ __forceinline__ uint32_t s2u(const void* p) {
    uint32_t a;
    asm("{.reg .u64 t; cvta.to.shared.u64 t,%1; cvt.u32.u64 %0,t;}" : "=r"(a) : "l"(p));
    return a;
}

__global__ void __launch_bounds__(TPB, 1)
lstm_kernel(const float* __restrict__ x,
            const float* __restrict__ w_ih1, const float* __restrict__ w_hh1,
            const float* __restrict__ b_ih1, const float* __restrict__ b_hh1,
            const float* __restrict__ w_ih2, const float* __restrict__ w_hh2,
            const float* __restrict__ b_ih2, const float* __restrict__ b_hh2) {
    // inputs as fp16 hi/lo pair-words: word m*8+n holds k=2m,2m+1 for batch n
    __shared__ uint32_t h1h[256], h1l[256], h2h[256], h2l[256];
    __shared__ uint32_t xh[2][128], xl[2][128];
    __shared__ float ga1[2080], ga2[2080];           // [b][row], stride 260
    __shared__ float xbuf[4096];                     // fp32 ring [2][8tl][8b][32k]

    const int tid = threadIdx.x;
    const int w   = tid >> 5, L = tid & 31;
    const int gr  = L >> 2,  q = L & 3;
    const int r1  = 16 * w + gr, r2 = r1 + 8;        // owned gate rows
    const int bo  = 8 * q + gr;                      // B-frag word offset in chunk
    const int b0  = blockIdx.x * 8;
    const int uu  = tid & 63, ub = tid >> 6;         // update ownership (unit,batch)

    // ---- weight A-fragments (fp16, registers) ----
    // g2 rows: [w_ih2 | w_hh2] (K=128, 8 chunks); g1 rows: [w_hh1 | w_ih1] (K=96, 6)
#define W2AT(r, k) ((k) < 64 ? w_ih2[(r) * 64 + (k)] : w_hh2[(r) * 64 + (k) - 64])
#define W1AT(r, k) ((k) < 64 ? w_hh1[(r) * 64 + (k)] : w_ih1[(r) * 32 + (k) - 64])
    uint32_t W2[8][4], W1[6][4];
#pragma unroll
    for (int c = 0; c < 8; c++) {
        int k0 = 16 * c + 2 * q;
        W2[c][0] = pkh(W2AT(r1, k0),     W2AT(r1, k0 + 1));
        W2[c][1] = pkh(W2AT(r2, k0),     W2AT(r2, k0 + 1));
        W2[c][2] = pkh(W2AT(r1, k0 + 8), W2AT(r1, k0 + 9));
        W2[c][3] = pkh(W2AT(r2, k0 + 8), W2AT(r2, k0 + 9));
    }
#pragma unroll
    for (int c = 0; c < 6; c++) {
        int k0 = 16 * c + 2 * q;
        W1[c][0] = pkh(W1AT(r1, k0),     W1AT(r1, k0 + 1));
        W1[c][1] = pkh(W1AT(r2, k0),     W1AT(r2, k0 + 1));
        W1[c][2] = pkh(W1AT(r1, k0 + 8), W1AT(r1, k0 + 9));
        W1[c][3] = pkh(W1AT(r2, k0 + 8), W1AT(r2, k0 + 9));
    }
    const float bs1a = b_ih1[r1] + b_hh1[r1], bs1b = b_ih1[r2] + b_hh1[r2];
    const float bs2a = b_ih2[r1] + b_hh2[r1], bs2b = b_ih2[r2] + b_hh2[r2];
    const bool  tg   = ((w >> 2) == 2);              // g-gate rows -> tanh

    if (tid < 256) { h1h[tid] = 0; h1l[tid] = 0; h2h[tid] = 0; h2l[tid] = 0; }

    // ---- x staging: cp.async fp32, chunks of 8 timesteps, 2-slot ring ----
    const int stl = tid >> 6, sb = (tid >> 3) & 7, skq = tid & 7;
    const float*   xs0 = x + ((size_t)(b0 + sb) * T_LEN + stl) * 32 + skq * 4;
    const uint32_t xd0 = s2u(xbuf) + (uint32_t)(((stl * 8 + sb) * 32 + skq * 4) * 4);
#define STG(c) do { cpa16(xd0 + (((c) & 1) ? 8192u : 0u), xs0 + (size_t)(c) * 256); \
                    asm volatile("cp.async.commit_group;"); } while (0)
#define XCONV(tn) if (tid < 128) { int m = tid & 15, bb = tid >> 4;                   \
        const float2 v = *(const float2*)&xbuf[((((tn) >> 3) & 1) * 8 + ((tn) & 7)) * 256 + bb * 32 + 2 * m]; \
        uint32_t hi, lo; hsplit2(v.x, v.y, hi, lo);                                   \
        xh[(tn) & 1][m * 8 + bb] = hi; xl[(tn) & 1][m * 8 + bb] = lo; }
#define HSTORE(arrh, arrl, hval) do {                                                 \
        __half hh = __float2half_rn(hval);                                            \
        __half hl = __float2half_rn((hval) - __half2float(hh));                       \
        ((__half*)(arrh))[((uu >> 1) * 8 + ub) * 2 + (uu & 1)] = hh;                  \
        ((__half*)(arrl))[((uu >> 1) * 8 + ub) * 2 + (uu & 1)] = hl; } while (0)
#define ACT4(d, ga, BA, BB) do {                                                      \
        float v0 = (d)[0] + (BA), v1 = (d)[1] + (BA);                                 \
        float v2 = (d)[2] + (BB), v3 = (d)[3] + (BB);                                 \
        if (tg) { v0 = tanhax(v0); v1 = tanhax(v1); v2 = tanhax(v2); v3 = tanhax(v3); }\
        else    { v0 = sigm(v0);   v1 = sigm(v1);   v2 = sigm(v2);   v3 = sigm(v3);  }\
        (ga)[(2 * q) * 260 + r1] = v0; (ga)[(2 * q + 1) * 260 + r1] = v1;             \
        (ga)[(2 * q) * 260 + r2] = v2; (ga)[(2 * q + 1) * 260 + r2] = v3; } while (0)

    STG(0); STG(1);
    asm volatile("cp.async.wait_group 0;");
    __syncthreads();
    XCONV(0);
    __syncthreads();

    float c1 = 0.0f, c2 = 0.0f;

    // ---- prologue: gates1(0) (h1 array is zero; x(0) in slot 0) ----
    {
        float e1[4] = {0.f, 0.f, 0.f, 0.f};
#pragma unroll
        for (int c = 0; c < 4; c++) {   // h1 part (zeros, cheap correctness)
            uint32_t bh0 = h1h[c * 64 + bo], bh1 = h1h[c * 64 + bo + 32];
            mma16(e1, W1[c], bh0, bh1);
        }
#pragma unroll
        for (int c = 0; c < 2; c++) {   // x part
            uint32_t bh0 = xh[0][c * 64 + bo], bh1 = xh[0][c * 64 + bo + 32];
            uint32_t bl0 = xl[0][c * 64 + bo], bl1 = xl[0][c * 64 + bo + 32];
            mma16(e1, W1[4 + c], bh0, bh1);
            mma16(e1, W1[4 + c], bl0, bl1);
        }
        ACT4(e1, ga1, bs1a, bs1b);
    }
    __syncthreads();
    {   // update1(0) -> h1(0); convert x(1)
        const float* g = ga1 + ub * 260;
        float i_ = g[uu], f_ = g[uu + 64], gv = g[uu + 128], o_ = g[uu + 192];
        c1 = fmaf(f_, c1, i_ * gv);
        float h = o_ * tanhax(c1);
        HSTORE(h1h, h1l, h);
    }
    XCONV(1);
    __syncthreads();

    // ---- main loop: round t = {g2(t), g1(t+1)} ----
    for (int t = 0; t < T_LEN; t++) {
        if ((t & 7) == 6) {
            asm volatile("cp.async.wait_group 0;");
            int c = (t + 2) >> 3;
            if (c + 1 < 128) STG(c + 1);
        }
        float d2[4] = {0.f, 0.f, 0.f, 0.f};
        float e1[4] = {0.f, 0.f, 0.f, 0.f};
        const uint32_t* xsh = xh[(t + 1) & 1];
        const uint32_t* xsl = xl[(t + 1) & 1];
#pragma unroll
        for (int c = 0; c < 4; c++) {   // shared h1(t) chunks feed g2 and g1
            uint32_t bh0 = h1h[c * 64 + bo], bh1 = h1h[c * 64 + bo + 32];
            uint32_t bl0 = h1l[c * 64 + bo], bl1 = h1l[c * 64 + bo + 32];
            mma16(d2, W2[c], bh0, bh1); mma16(d2, W2[c], bl0, bl1);
            mma16(e1, W1[c], bh0, bh1); mma16(e1, W1[c], bl0, bl1);
        }
#pragma unroll
        for (int c = 0; c < 4; c++) {   // h2(t-1) chunks for g2
            uint32_t bh0 = h2h[c * 64 + bo], bh1 = h2h[c * 64 + bo + 32];
            uint32_t bl0 = h2l[c * 64 + bo], bl1 = h2l[c * 64 + bo + 32];
            mma16(d2, W2[4 + c], bh0, bh1); mma16(d2, W2[4 + c], bl0, bl1);
        }
#pragma unroll
        for (int c = 0; c < 2; c++) {   // x(t+1) chunks for g1
            uint32_t bh0 = xsh[c * 64 + bo], bh1 = xsh[c * 64 + bo + 32];
            uint32_t bl0 = xsl[c * 64 + bo], bl1 = xsl[c * 64 + bo + 32];
            mma16(e1, W1[4 + c], bh0, bh1); mma16(e1, W1[4 + c], bl0, bl1);
        }
        ACT4(d2, ga2, bs2a, bs2b);
        ACT4(e1, ga1, bs1a, bs1b);
        __syncthreads();

        {   // update2(t)
            const float* g = ga2 + ub * 260;
            float i_ = g[uu], f_ = g[uu + 64], gv = g[uu + 128], o_ = g[uu + 192];
            c2 = fmaf(f_, c2, i_ * gv);
            float h = o_ * tanhax(c2);
            HSTORE(h2h, h2l, h);
            if (t == T_LEN - 1) g_h2[(size_t)(b0 + ub) * 64 + uu] = h;
        }
        {   // update1(t+1) (garbage at t=1023; never read)
            const float* g = ga1 + ub * 260;
            float i_ = g[uu], f_ = g[uu + 64], gv = g[uu + 128], o_ = g[uu + 192];
            c1 = fmaf(f_, c1, i_ * gv);
            float h = o_ * tanhax(c1);
            HSTORE(h1h, h1l, h);
        }
        if (t + 2 < T_LEN) XCONV(t + 2);
        __syncthreads();
    }
#undef STG
#undef XCONV
#undef HSTORE
#undef ACT4
}

// ---------------- head: LN(relu(h@fc1^T+b1)@fc2^T+b2) ----------------
#define HB 4
__global__ void __launch_bounds__(128)
head_kernel(const float* __restrict__ fc1_w, const float* __restrict__ fc1_b,
            const float* __restrict__ fc2_w, const float* __restrict__ fc2_b,
            const float* __restrict__ ln_g,  const float* __restrict__ ln_b,
            float* __restrict__ out) {
    extern __shared__ float hs[];
    float* w1 = hs;                  // 128*65
    float* w2 = w1 + 128 * 65;       // 128*129
    float* hv = w2 + 128 * 129;      // HB*64
    float* y1 = hv + HB * 64;        // 128
    float* rs = y1 + 128;            // 4
    float* rq = rs + 4;              // 4
    const int tid = threadIdx.x, b0 = blockIdx.x * HB;

    for (int i = tid; i < 8192;  i += 128) w1[(i >> 6) * 65  + (i & 63)]  = fc1_w[i];
    for (int i = tid; i < 16384; i += 128) w2[(i >> 7) * 129 + (i & 127)] = fc2_w[i];
    for (int i = tid; i < HB * 64; i += 128) hv[i] = g_h2[(size_t)b0 * 64 + i];
    const float b1v = fc1_b[tid], b2v = fc2_b[tid];
    const float gv = ln_g[tid],   bv = ln_b[tid];
    __syncthreads();

    float a2v[HB];
#pragma unroll 1
    for (int bb = 0; bb < HB; bb++) {
        float s0 = b1v, s1 = 0.f;
#pragma unroll
        for (int k = 0; k < 64; k += 2) {
            s0 = fmaf(hv[bb * 64 + k],     w1[tid * 65 + k],     s0);
            s1 = fmaf(hv[bb * 64 + k + 1], w1[tid * 65 + k + 1], s1);
        }
        y1[tid] = fmaxf(s0 + s1, 0.0f);
        __syncthreads();
        float t0 = b2v, t1 = 0.f;
#pragma unroll
        for (int k = 0; k < 128; k += 2) {
            t0 = fmaf(y1[k],     w2[tid * 129 + k],     t0);
            t1 = fmaf(y1[k + 1], w2[tid * 129 + k + 1], t1);
        }
        a2v[bb] = t0 + t1;
        __syncthreads();
    }
#pragma unroll 1
    for (int bb = 0; bb < HB; bb++) {
        float sv = a2v[bb], sq = a2v[bb] * a2v[bb];
#pragma unroll
        for (int o = 16; o > 0; o >>= 1) {
            sv += __shfl_xor_sync(0xffffffffu, sv, o);
            sq += __shfl_xor_sync(0xffffffffu, sq, o);
        }
        if ((tid & 31) == 0) { rs[tid >> 5] = sv; rq[tid >> 5] = sq; }
        __syncthreads();
        float S = rs[0] + rs[1] + rs[2] + rs[3];
        float Q = rq[0] + rq[1] + rq[2] + rq[3];
        float mu  = S * (1.0f / 128.0f);
        float var = Q * (1.0f / 128.0f) - mu * mu;
        out[(size_t)(b0 + bb) * 128 + tid] =
            (a2v[bb] - mu) * rsqrtf(var + 1e-5f) * gv + bv;
        __syncthreads();
    }
}

extern "C" void kernel_launch(void* const* d_in, const int* in_sizes, int n_in,
                              void* d_out, int out_size) {
    const float* x     = (const float*)d_in[0];
    const float* w_ih1 = (const float*)d_in[1];
    const float* w_hh1 = (const float*)d_in[2];
    const float* b_ih1 = (const float*)d_in[3];
    const float* b_hh1 = (const float*)d_in[4];
    const float* w_ih2 = (const float*)d_in[5];
    const float* w_hh2 = (const float*)d_in[6];
    const float* b_ih2 = (const float*)d_in[7];
    const float* b_hh2 = (const float*)d_in[8];
    const float* fc1_w = (const float*)d_in[9];
    const float* fc1_b = (const float*)d_in[10];
    const float* fc2_w = (const float*)d_in[11];
    const float* fc2_b = (const float*)d_in[12];
    const float* ln_g  = (const float*)d_in[13];
    const float* ln_b  = (const float*)d_in[14];
    float* out = (float*)d_out;

    lstm_kernel<<<CTAS, TPB>>>(x, w_ih1, w_hh1, b_ih1, b_hh1,
                               w_ih2, w_hh2, b_ih2, b_hh2);

    int head_smem = (128 * 65 + 128 * 129 + HB * 64 + 128 + 8) * (int)sizeof(float);
    cudaFuncSetAttribute(head_kernel,
                         cudaFuncAttributeMaxDynamicSharedMemorySize, head_smem);
    head_kernel<<<512 / HB, 128, head_smem>>>(fc1_w, fc1_b, fc2_w, fc2_b,
                                              ln_g, ln_b, out);
}

// round 7
// speedup vs baseline: 3.8250x; 1.4515x over previous
#include <cuda_runtime.h>
#include <cuda_fp16.h>
#include <cstdint>

// R7: single-pass fp16 mma.sync persistent 2-layer LSTM (lo-pass removed).
// 64 CTAs x 512 thr, 8 batch/CTA. Weights = fp16 A-fragments in registers.
// Round t = {gates2(t), gates1(t+1)}; 2 barriers/round.

#define CTAS  64
#define TPB   512
#define T_LEN 1024

static __device__ float g_h2[512 * 64];

__device__ __forceinline__ uint32_t pkh(float a, float b) {
    __half ha = __float2half_rn(a), hb = __float2half_rn(b);
    return (uint32_t)__half_as_ushort(ha) | ((uint32_t)__half_as_ushort(hb) << 16);
}
__device__ __forceinline__ float tanhax(float x) {
    float y; asm("tanh.approx.f32 %0,%1;" : "=f"(y) : "f"(x)); return y;
}
__device__ __forceinline__ float sigm(float x) { return fmaf(tanhax(0.5f * x), 0.5f, 0.5f); }

__device__ __forceinline__ void mma16(float* d, const uint32_t* a, uint32_t b0, uint32_t b1) {
    asm volatile(
        "mma.sync.aligned.m16n8k16.row.col.f32.f16.f16.f32 "
        "{%0,%1,%2,%3},{%4,%5,%6,%7},{%8,%9},{%0,%1,%2,%3};"
        : "+f"(d[0]), "+f"(d[1]), "+f"(d[2]), "+f"(d[3])
        : "r"(a[0]), "r"(a[1]), "r"(a[2]), "r"(a[3]), "r"(b0), "r"(b1));
}
__device__ __forceinline__ void cpa16(uint32_t d, const void* s) {
    asm volatile("cp.async.ca.shared.global [%0],[%1],16;" :: "r"(d), "l"(s));
}
__device__ __forceinline__ uint32_t s2u(const void* p) {
    uint32_t a;
    asm("{.reg .u64 t; cvta.to.shared.u64 t,%1; cvt.u32.u64 %0,t;}" : "=r"(a) : "l"(p));
    return a;
}

__global__ void __launch_bounds__(TPB, 1)
lstm_kernel(const float* __restrict__ x,
            const float* __restrict__ w_ih1, const float* __restrict__ w_hh1,
            const float* __restrict__ b_ih1, const float* __restrict__ b_hh1,
            const float* __restrict__ w_ih2, const float* __restrict__ w_hh2,
            const float* __restrict__ b_ih2, const float* __restrict__ b_hh2) {
    // inputs as fp16 pair-words: word m*8+n holds k=2m,2m+1 for batch n
    __shared__ uint32_t h1v[256], h2v[256];
    __shared__ uint32_t xv[2][128];
    __shared__ float ga1[2080], ga2[2080];           // [b][row], stride 260
    __shared__ float xbuf[4096];                     // fp32 ring [2][8tl][8b][32k]

    const int tid = threadIdx.x;
    const int w   = tid >> 5, L = tid & 31;
    const int gr  = L >> 2,  q = L & 3;
    const int r1  = 16 * w + gr, r2 = r1 + 8;        // owned gate rows
    const int bo  = 8 * q + gr;                      // B-frag word offset in chunk
    const int b0  = blockIdx.x * 8;
    const int uu  = tid & 63, ub = tid >> 6;         // update ownership (unit,batch)

    // ---- weight A-fragments (fp16, registers) ----
#define W2AT(r, k) ((k) < 64 ? w_ih2[(r) * 64 + (k)] : w_hh2[(r) * 64 + (k) - 64])
#define W1AT(r, k) ((k) < 64 ? w_hh1[(r) * 64 + (k)] : w_ih1[(r) * 32 + (k) - 64])
    uint32_t W2[8][4], W1[6][4];
#pragma unroll
    for (int c = 0; c < 8; c++) {
        int k0 = 16 * c + 2 * q;
        W2[c][0] = pkh(W2AT(r1, k0),     W2AT(r1, k0 + 1));
        W2[c][1] = pkh(W2AT(r2, k0),     W2AT(r2, k0 + 1));
        W2[c][2] = pkh(W2AT(r1, k0 + 8), W2AT(r1, k0 + 9));
        W2[c][3] = pkh(W2AT(r2, k0 + 8), W2AT(r2, k0 + 9));
    }
#pragma unroll
    for (int c = 0; c < 6; c++) {
        int k0 = 16 * c + 2 * q;
        W1[c][0] = pkh(W1AT(r1, k0),     W1AT(r1, k0 + 1));
        W1[c][1] = pkh(W1AT(r2, k0),     W1AT(r2, k0 + 1));
        W1[c][2] = pkh(W1AT(r1, k0 + 8), W1AT(r1, k0 + 9));
        W1[c][3] = pkh(W1AT(r2, k0 + 8), W1AT(r2, k0 + 9));
    }
    const float bs1a = b_ih1[r1] + b_hh1[r1], bs1b = b_ih1[r2] + b_hh1[r2];
    const float bs2a = b_ih2[r1] + b_hh2[r1], bs2b = b_ih2[r2] + b_hh2[r2];
    const bool  tg   = ((w >> 2) == 2);              // g-gate rows -> tanh

    if (tid < 256) { h1v[tid] = 0; h2v[tid] = 0; }

    // ---- x staging: cp.async fp32, chunks of 8 timesteps, 2-slot ring ----
    const int stl = tid >> 6, sb = (tid >> 3) & 7, skq = tid & 7;
    const float*   xs0 = x + ((size_t)(b0 + sb) * T_LEN + stl) * 32 + skq * 4;
    const uint32_t xd0 = s2u(xbuf) + (uint32_t)(((stl * 8 + sb) * 32 + skq * 4) * 4);
#define STG(c) do { cpa16(xd0 + (((c) & 1) ? 8192u : 0u), xs0 + (size_t)(c) * 256); \
                    asm volatile("cp.async.commit_group;"); } while (0)
#define XCONV(tn) if (tid < 128) { int m = tid & 15, bb = tid >> 4;                   \
        const float2 v = *(const float2*)&xbuf[((((tn) >> 3) & 1) * 8 + ((tn) & 7)) * 256 + bb * 32 + 2 * m]; \
        xv[(tn) & 1][m * 8 + bb] = pkh(v.x, v.y); }
#define HSTORE(arr, hval) \
        ((__half*)(arr))[((uu >> 1) * 8 + ub) * 2 + (uu & 1)] = __float2half_rn(hval)
#define ACT4(d, ga, BA, BB) do {                                                      \
        float v0 = (d)[0] + (BA), v1 = (d)[1] + (BA);                                 \
        float v2 = (d)[2] + (BB), v3 = (d)[3] + (BB);                                 \
        if (tg) { v0 = tanhax(v0); v1 = tanhax(v1); v2 = tanhax(v2); v3 = tanhax(v3); }\
        else    { v0 = sigm(v0);   v1 = sigm(v1);   v2 = sigm(v2);   v3 = sigm(v3);  }\
        (ga)[(2 * q) * 260 + r1] = v0; (ga)[(2 * q + 1) * 260 + r1] = v1;             \
        (ga)[(2 * q) * 260 + r2] = v2; (ga)[(2 * q + 1) * 260 + r2] = v3; } while (0)

    STG(0); STG(1);
    asm volatile("cp.async.wait_group 0;");
    __syncthreads();
    XCONV(0);
    __syncthreads();

    float c1 = 0.0f, c2 = 0.0f;

    // ---- prologue: gates1(0) (h1 zero; x(0) in slot 0) ----
    {
        float e1[4] = {0.f, 0.f, 0.f, 0.f};
#pragma unroll
        for (int c = 0; c < 2; c++) {
            uint32_t b0w = xv[0][c * 64 + bo], b1w = xv[0][c * 64 + bo + 32];
            mma16(e1, W1[4 + c], b0w, b1w);
        }
        ACT4(e1, ga1, bs1a, bs1b);
    }
    __syncthreads();
    {   // update1(0) -> h1(0); convert x(1)
        const float* g = ga1 + ub * 260;
        float i_ = g[uu], f_ = g[uu + 64], gv = g[uu + 128], o_ = g[uu + 192];
        c1 = fmaf(f_, c1, i_ * gv);
        HSTORE(h1v, o_ * tanhax(c1));
    }
    XCONV(1);
    __syncthreads();

    // ---- main loop: round t = {g2(t), g1(t+1)} ----
    for (int t = 0; t < T_LEN; t++) {
        if ((t & 7) == 6) {
            asm volatile("cp.async.wait_group 0;");
            int c = (t + 2) >> 3;
            if (c + 1 < 128) STG(c + 1);
        }
        float d2[4] = {0.f, 0.f, 0.f, 0.f};
        float e1[4] = {0.f, 0.f, 0.f, 0.f};
        const uint32_t* xs = xv[(t + 1) & 1];
#pragma unroll
        for (int c = 0; c < 4; c++) {   // h1(t) chunks feed g2 and g1
            uint32_t b0w = h1v[c * 64 + bo], b1w = h1v[c * 64 + bo + 32];
            mma16(d2, W2[c], b0w, b1w);
            mma16(e1, W1[c], b0w, b1w);
        }
#pragma unroll
        for (int c = 0; c < 4; c++) {   // h2(t-1) chunks for g2
            uint32_t b0w = h2v[c * 64 + bo], b1w = h2v[c * 64 + bo + 32];
            mma16(d2, W2[4 + c], b0w, b1w);
        }
#pragma unroll
        for (int c = 0; c < 2; c++) {   // x(t+1) chunks for g1
            uint32_t b0w = xs[c * 64 + bo], b1w = xs[c * 64 + bo + 32];
            mma16(e1, W1[4 + c], b0w, b1w);
        }
        ACT4(d2, ga2, bs2a, bs2b);
        ACT4(e1, ga1, bs1a, bs1b);
        __syncthreads();

        {   // update2(t)
            const float* g = ga2 + ub * 260;
            float i_ = g[uu], f_ = g[uu + 64], gv = g[uu + 128], o_ = g[uu + 192];
            c2 = fmaf(f_, c2, i_ * gv);
            float h = o_ * tanhax(c2);
            HSTORE(h2v, h);
            if (t == T_LEN - 1) g_h2[(size_t)(b0 + ub) * 64 + uu] = h;
        }
        {   // update1(t+1) (garbage at t=1023; never read)
            const float* g = ga1 + ub * 260;
            float i_ = g[uu], f_ = g[uu + 64], gv = g[uu + 128], o_ = g[uu + 192];
            c1 = fmaf(f_, c1, i_ * gv);
            HSTORE(h1v, o_ * tanhax(c1));
        }
        if (t + 2 < T_LEN) XCONV(t + 2);
        __syncthreads();
    }
#undef STG
#undef XCONV
#undef HSTORE
#undef ACT4
}

// ---------------- head: LN(relu(h@fc1^T+b1)@fc2^T+b2) ----------------
#define HB 4
__global__ void __launch_bounds__(128)
head_kernel(const float* __restrict__ fc1_w, const float* __restrict__ fc1_b,
            const float* __restrict__ fc2_w, const float* __restrict__ fc2_b,
            const float* __restrict__ ln_g,  const float* __restrict__ ln_b,
            float* __restrict__ out) {
    extern __shared__ float hs[];
    float* w1 = hs;                  // 128*65
    float* w2 = w1 + 128 * 65;       // 128*129
    float* hv = w2 + 128 * 129;      // HB*64
    float* y1 = hv + HB * 64;        // 128
    float* rs = y1 + 128;            // 4
    float* rq = rs + 4;              // 4
    const int tid = threadIdx.x, b0 = blockIdx.x * HB;

    for (int i = tid; i < 8192;  i += 128) w1[(i >> 6) * 65  + (i & 63)]  = fc1_w[i];
    for (int i = tid; i < 16384; i += 128) w2[(i >> 7) * 129 + (i & 127)] = fc2_w[i];
    for (int i = tid; i < HB * 64; i += 128) hv[i] = g_h2[(size_t)b0 * 64 + i];
    const float b1v = fc1_b[tid], b2v = fc2_b[tid];
    const float gv = ln_g[tid],   bv = ln_b[tid];
    __syncthreads();

    float a2v[HB];
#pragma unroll 1
    for (int bb = 0; bb < HB; bb++) {
        float s0 = b1v, s1 = 0.f;
#pragma unroll
        for (int k = 0; k < 64; k += 2) {
            s0 = fmaf(hv[bb * 64 + k],     w1[tid * 65 + k],     s0);
            s1 = fmaf(hv[bb * 64 + k + 1], w1[tid * 65 + k + 1], s1);
        }
        y1[tid] = fmaxf(s0 + s1, 0.0f);
        __syncthreads();
        float t0 = b2v, t1 = 0.f;
#pragma unroll
        for (int k = 0; k < 128; k += 2) {
            t0 = fmaf(y1[k],     w2[tid * 129 + k],     t0);
            t1 = fmaf(y1[k + 1], w2[tid * 129 + k + 1], t1);
        }
        a2v[bb] = t0 + t1;
        __syncthreads();
    }
#pragma unroll 1
    for (int bb = 0; bb < HB; bb++) {
        float sv = a2v[bb], sq = a2v[bb] * a2v[bb];
#pragma unroll
        for (int o = 16; o > 0; o >>= 1) {
            sv += __shfl_xor_sync(0xffffffffu, sv, o);
            sq += __shfl_xor_sync(0xffffffffu, sq, o);
        }
        if ((tid & 31) == 0) { rs[tid >> 5] = sv; rq[tid >> 5] = sq; }
        __syncthreads();
        float S = rs[0] + rs[1] + rs[2] + rs[3];
        float Q = rq[0] + rq[1] + rq[2] + rq[3];
        float mu  = S * (1.0f / 128.0f);
        float var = Q * (1.0f / 128.0f) - mu * mu;
        out[(size_t)(b0 + bb) * 128 + tid] =
            (a2v[bb] - mu) * rsqrtf(var + 1e-5f) * gv + bv;
        __syncthreads();
    }
}

extern "C" void kernel_launch(void* const* d_in, const int* in_sizes, int n_in,
                              void* d_out, int out_size) {
    const float* x     = (const float*)d_in[0];
    const float* w_ih1 = (const float*)d_in[1];
    const float* w_hh1 = (const float*)d_in[2];
    const float* b_ih1 = (const float*)d_in[3];
    const float* b_hh1 = (const float*)d_in[4];
    const float* w_ih2 = (const float*)d_in[5];
    const float* w_hh2 = (const float*)d_in[6];
    const float* b_ih2 = (const float*)d_in[7];
    const float* b_hh2 = (const float*)d_in[8];
    const float* fc1_w = (const float*)d_in[9];
    const float* fc1_b = (const float*)d_in[10];
    const float* fc2_w = (const float*)d_in[11];
    const float* fc2_b = (const float*)d_in[12];
    const float* ln_g  = (const float*)d_in[13];
    const float* ln_b  = (const float*)d_in[14];
    float* out = (float*)d_out;

    lstm_kernel<<<CTAS, TPB>>>(x, w_ih1, w_hh1, b_ih1, b_hh1,
                               w_ih2, w_hh2, b_ih2, b_hh2);

    int head_smem = (128 * 65 + 128 * 129 + HB * 64 + 128 + 8) * (int)sizeof(float);
    cudaFuncSetAttribute(head_kernel,
                         cudaFuncAttributeMaxDynamicSharedMemorySize, head_smem);
    head_kernel<<<512 / HB, 128, head_smem>>>(fc1_w, fc1_b, fc2_w, fc2_b,
                                              ln_g, ln_b, out);
}

// round 8
// speedup vs baseline: 4.7520x; 1.2423x over previous
#include <cuda_runtime.h>
#include <cuda_fp16.h>
#include <cstdint>

// R8: warp-specialized fp16 HMMA persistent LSTM.
// Group A (warps 0-7): layer2 gates+update, h2 private.
// Group B (warps 8-15): layer1 gates+update, writes double-buffered h1.
// 1 full barrier + 1 named 256-thread barrier per round.
// x pre-converted to fp16 B-fragment layout by xconv_kernel.

#define CTAS  64
#define TPB   512
#define T_LEN 1024

static __device__ float    g_h2[512 * 64];
static __device__ uint32_t g_xh[64 * 1024 * 128];   // [gb][t][word] fp16 pairs

__device__ __forceinline__ uint32_t pkh(float a, float b) {
    __half ha = __float2half_rn(a), hb = __float2half_rn(b);
    return (uint32_t)__half_as_ushort(ha) | ((uint32_t)__half_as_ushort(hb) << 16);
}
__device__ __forceinline__ float tanhax(float x) {
    float y; asm("tanh.approx.f32 %0,%1;" : "=f"(y) : "f"(x)); return y;
}
__device__ __forceinline__ uint32_t cvt2h(float hi, float lo) {  // lo -> low half
    uint32_t r; asm("cvt.rn.f16x2.f32 %0,%1,%2;" : "=r"(r) : "f"(hi), "f"(lo)); return r;
}
__device__ __forceinline__ uint32_t tanh2(uint32_t v) {
    uint32_t r; asm("tanh.approx.f16x2 %0,%1;" : "=r"(r) : "r"(v)); return r;
}
__device__ __forceinline__ uint32_t tanh2_from(float lo, float hi) {
    return tanh2(cvt2h(hi, lo));
}
__device__ __forceinline__ uint32_t sig2_from(float lo, float hi) {
    uint32_t t = tanh2(cvt2h(0.5f * hi, 0.5f * lo));
    uint32_t r;
    asm("fma.rn.f16x2 %0,%1,%2,%3;" : "=r"(r)
        : "r"(t), "r"(0x38003800u), "r"(0x38003800u));   // *0.5 + 0.5
    return r;
}
__device__ __forceinline__ void mma16(float* d, const uint32_t* a, uint32_t b0, uint32_t b1) {
    asm volatile(
        "mma.sync.aligned.m16n8k16.row.col.f32.f16.f16.f32 "
        "{%0,%1,%2,%3},{%4,%5,%6,%7},{%8,%9},{%0,%1,%2,%3};"
        : "+f"(d[0]), "+f"(d[1]), "+f"(d[2]), "+f"(d[3])
        : "r"(a[0]), "r"(a[1]), "r"(a[2]), "r"(a[3]), "r"(b0), "r"(b1));
}
__device__ __forceinline__ void cpa16(uint32_t d, const void* s) {
    asm volatile("cp.async.ca.shared.global [%0],[%1],16;" :: "r"(d), "l"(s));
}
__device__ __forceinline__ uint32_t s2u(const void* p) {
    uint32_t a;
    asm("{.reg .u64 t; cvta.to.shared.u64 t,%1; cvt.u32.u64 %0,t;}" : "=r"(a) : "l"(p));
    return a;
}

// ---- x pre-conversion: fp32 [B][T][32] -> fp16-pair words [gb][t][m*8+n] ----
__global__ void __launch_bounds__(256)
xconv_kernel(const float* __restrict__ x) {
    int id = blockIdx.x * 256 + threadIdx.x;      // one word each
    int word = id & 127, t = (id >> 7) & 1023, gb = id >> 17;
    int m = word >> 3, n = word & 7;
    const float2 v = *(const float2*)&x[(((size_t)(gb * 8 + n)) * 1024 + t) * 32 + 2 * m];
    g_xh[(size_t)id] = pkh(v.x, v.y);
}

__global__ void __launch_bounds__(TPB, 1)
lstm_kernel(const float* __restrict__ w_ih1, const float* __restrict__ w_hh1,
            const float* __restrict__ b_ih1, const float* __restrict__ b_hh1,
            const float* __restrict__ w_ih2, const float* __restrict__ w_hh2,
            const float* __restrict__ b_ih2, const float* __restrict__ b_hh2) {
    __shared__ uint32_t h1d[2][256];     // double-buffered h1, fp16 pair words
    __shared__ uint32_t h2v[256];        // h2 (group A private)
    __shared__ uint32_t xv[8][128];      // x ring, 8 steps
    __shared__ uint32_t ga2h[1024];      // [j][row] half2 gates, layer2
    __shared__ uint32_t ga1h[1024];      // layer1

    const int tid = threadIdx.x;
    const int w   = tid >> 5, L = tid & 31;
    const int wg  = w & 7;
    const int gr  = L >> 2, q = L & 3;
    const int r1  = 32 * wg + gr, r2 = r1 + 8, r3 = r1 + 16, r4 = r1 + 24;
    const int bo  = 8 * q + gr;
    const bool isA = (w < 8);
    const bool tg  = ((wg >> 1) == 2);           // rows 128..191 -> tanh
    const int tl  = isA ? tid : tid - 256;       // local id within group
    const int uu  = tl & 63, j = tl >> 6;        // update: unit, batch-pair

    // ---- weight fragments (union storage: A uses W2, B uses W1) ----
    uint32_t WF[16][4];
    float bb1, bb2, bb3, bb4;
#define W2AT(r, k) ((k) < 64 ? w_ih2[(r) * 64 + (k)] : w_hh2[(r) * 64 + (k) - 64])
#define W1AT(r, k) ((k) < 64 ? w_hh1[(r) * 64 + (k)] : w_ih1[(r) * 32 + (k) - 64])
    if (isA) {
#pragma unroll
        for (int c = 0; c < 8; c++) {
            int k0 = 16 * c + 2 * q;
            WF[c][0] = pkh(W2AT(r1, k0),     W2AT(r1, k0 + 1));
            WF[c][1] = pkh(W2AT(r2, k0),     W2AT(r2, k0 + 1));
            WF[c][2] = pkh(W2AT(r1, k0 + 8), W2AT(r1, k0 + 9));
            WF[c][3] = pkh(W2AT(r2, k0 + 8), W2AT(r2, k0 + 9));
            WF[8 + c][0] = pkh(W2AT(r3, k0),     W2AT(r3, k0 + 1));
            WF[8 + c][1] = pkh(W2AT(r4, k0),     W2AT(r4, k0 + 1));
            WF[8 + c][2] = pkh(W2AT(r3, k0 + 8), W2AT(r3, k0 + 9));
            WF[8 + c][3] = pkh(W2AT(r4, k0 + 8), W2AT(r4, k0 + 9));
        }
        bb1 = b_ih2[r1] + b_hh2[r1]; bb2 = b_ih2[r2] + b_hh2[r2];
        bb3 = b_ih2[r3] + b_hh2[r3]; bb4 = b_ih2[r4] + b_hh2[r4];
    } else {
#pragma unroll
        for (int c = 0; c < 6; c++) {
            int k0 = 16 * c + 2 * q;
            WF[c][0] = pkh(W1AT(r1, k0),     W1AT(r1, k0 + 1));
            WF[c][1] = pkh(W1AT(r2, k0),     W1AT(r2, k0 + 1));
            WF[c][2] = pkh(W1AT(r1, k0 + 8), W1AT(r1, k0 + 9));
            WF[c][3] = pkh(W1AT(r2, k0 + 8), W1AT(r2, k0 + 9));
            WF[8 + c][0] = pkh(W1AT(r3, k0),     W1AT(r3, k0 + 1));
            WF[8 + c][1] = pkh(W1AT(r4, k0),     W1AT(r4, k0 + 1));
            WF[8 + c][2] = pkh(W1AT(r3, k0 + 8), W1AT(r3, k0 + 9));
            WF[8 + c][3] = pkh(W1AT(r4, k0 + 8), W1AT(r4, k0 + 9));
        }
        bb1 = b_ih1[r1] + b_hh1[r1]; bb2 = b_ih1[r2] + b_hh1[r2];
        bb3 = b_ih1[r3] + b_hh1[r3]; bb4 = b_ih1[r4] + b_hh1[r4];
    }

    if (tid < 256) { h1d[0][tid] = 0; h1d[1][tid] = 0; h2v[tid] = 0; }

    // ---- prologue x staging: steps 0..7 ----
    const size_t xg = (size_t)blockIdx.x * 1024 * 128;
    const uint32_t xvb = s2u(xv);
    if (w == 8) {
#pragma unroll
        for (int s = 0; s < 8; s++) {
            cpa16(xvb + (uint32_t)((s * 128 + L * 4) * 4), &g_xh[xg + s * 128 + L * 4]);
            asm volatile("cp.async.commit_group;");
        }
        asm volatile("cp.async.wait_group 0;");
    }
    __syncthreads();

    float cx = 0.0f, cy = 0.0f;    // c2 (A) / c1 (B) for batches 2j, 2j+1

#define ACT_STORE(ga, d0, d1, d2_, d3, rA, rB, bA, bB) do {                    \
        if (tg) { (ga)[q * 256 + (rA)] = tanh2_from((d0) + (bA), (d1) + (bA)); \
                  (ga)[q * 256 + (rB)] = tanh2_from((d2_) + (bB), (d3) + (bB)); } \
        else    { (ga)[q * 256 + (rA)] = sig2_from((d0) + (bA), (d1) + (bA));  \
                  (ga)[q * 256 + (rB)] = sig2_from((d2_) + (bB), (d3) + (bB)); } } while (0)

#define UPDATE(ga, harr) do {                                                  \
        uint32_t wi = (ga)[j * 256 + uu],        wf = (ga)[j * 256 + 64 + uu]; \
        uint32_t wg_ = (ga)[j * 256 + 128 + uu], wo = (ga)[j * 256 + 192 + uu];\
        float2 fi = __half22float2(*(__half2*)&wi);                            \
        float2 ff = __half22float2(*(__half2*)&wf);                            \
        float2 fg = __half22float2(*(__half2*)&wg_);                           \
        float2 fo = __half22float2(*(__half2*)&wo);                            \
        cx = fmaf(ff.x, cx, fi.x * fg.x);                                      \
        cy = fmaf(ff.y, cy, fi.y * fg.y);                                      \
        hx = fo.x * tanhax(cx); hy = fo.y * tanhax(cy);                        \
        __half* hp = (__half*)(harr);                                          \
        hp[(((uu >> 1) * 8 + 2 * j) << 1)     | (uu & 1)] = __float2half_rn(hx);\
        hp[(((uu >> 1) * 8 + 2 * j + 1) << 1) | (uu & 1)] = __float2half_rn(hy);\
    } while (0)

    // ---- prologue: B computes g1(0) (h1(-1)=0 via zeroed h1d[1]) ----
    if (!isA) {
        float da[4] = {0,0,0,0}, db[4] = {0,0,0,0};
        const uint32_t* h1c = h1d[1];
#pragma unroll
        for (int c = 0; c < 4; c++) {
            uint32_t b0w = h1c[c * 64 + bo], b1w = h1c[c * 64 + bo + 32];
            mma16(da, WF[c], b0w, b1w); mma16(db, WF[8 + c], b0w, b1w);
        }
#pragma unroll
        for (int c = 0; c < 2; c++) {
            uint32_t b0w = xv[0][c * 64 + bo], b1w = xv[0][c * 64 + bo + 32];
            mma16(da, WF[4 + c], b0w, b1w); mma16(db, WF[12 + c], b0w, b1w);
        }
        ACT_STORE(ga1h, da[0], da[1], da[2], da[3], r1, r2, bb1, bb2);
        ACT_STORE(ga1h, db[0], db[1], db[2], db[3], r3, r4, bb3, bb4);
        asm volatile("bar.sync 2, 256;" ::: "memory");
        float hx, hy;
        UPDATE(ga1h, h1d[0]);
    }
    __syncthreads();

    // =================== main loop ===================
    for (int t = 0; t < T_LEN; t++) {
        if (isA) {
            // ---- gates2(t): h1(t) + h2(t-1) ----
            float da[4] = {0,0,0,0}, db[4] = {0,0,0,0};
            const uint32_t* h1c = h1d[t & 1];
#pragma unroll
            for (int c = 0; c < 4; c++) {
                uint32_t b0w = h1c[c * 64 + bo], b1w = h1c[c * 64 + bo + 32];
                mma16(da, WF[c], b0w, b1w); mma16(db, WF[8 + c], b0w, b1w);
            }
#pragma unroll
            for (int c = 0; c < 4; c++) {
                uint32_t b0w = h2v[c * 64 + bo], b1w = h2v[c * 64 + bo + 32];
                mma16(da, WF[4 + c], b0w, b1w); mma16(db, WF[12 + c], b0w, b1w);
            }
            ACT_STORE(ga2h, da[0], da[1], da[2], da[3], r1, r2, bb1, bb2);
            ACT_STORE(ga2h, db[0], db[1], db[2], db[3], r3, r4, bb3, bb4);
            asm volatile("bar.sync 1, 256;" ::: "memory");
            float hx, hy;
            UPDATE(ga2h, h2v);
            if (t == T_LEN - 1) {
                g_h2[(size_t)(blockIdx.x * 8 + 2 * j) * 64 + uu]     = hx;
                g_h2[(size_t)(blockIdx.x * 8 + 2 * j + 1) * 64 + uu] = hy;
            }
        } else {
            // ---- stage x(t+8) ----
            if (w == 8) {
                int st = t + 8; if (st > 1023) st = 1023;
                cpa16(xvb + (uint32_t)((((st & 7) * 128) + L * 4) * 4),
                      &g_xh[xg + (size_t)st * 128 + L * 4]);
                asm volatile("cp.async.commit_group;");
            }
            // ---- gates1(t+1): h1(t) + x(t+1) ----
            float da[4] = {0,0,0,0}, db[4] = {0,0,0,0};
            const uint32_t* h1c = h1d[t & 1];
            const uint32_t* xs  = xv[(t + 1) & 7];
#pragma unroll
            for (int c = 0; c < 4; c++) {
                uint32_t b0w = h1c[c * 64 + bo], b1w = h1c[c * 64 + bo + 32];
                mma16(da, WF[c], b0w, b1w); mma16(db, WF[8 + c], b0w, b1w);
            }
#pragma unroll
            for (int c = 0; c < 2; c++) {
                uint32_t b0w = xs[c * 64 + bo], b1w = xs[c * 64 + bo + 32];
                mma16(da, WF[4 + c], b0w, b1w); mma16(db, WF[12 + c], b0w, b1w);
            }
            ACT_STORE(ga1h, da[0], da[1], da[2], da[3], r1, r2, bb1, bb2);
            ACT_STORE(ga1h, db[0], db[1], db[2], db[3], r3, r4, bb3, bb4);
            asm volatile("bar.sync 2, 256;" ::: "memory");
            float hx, hy;
            UPDATE(ga1h, h1d[(t + 1) & 1]);   // garbage at t=1023, never read
            if (w == 8) asm volatile("cp.async.wait_group 6;");
        }
        __syncthreads();
    }
#undef ACT_STORE
#undef UPDATE
}

// ---------------- head: LN(relu(h@fc1^T+b1)@fc2^T+b2) ----------------
#define HB 4
__global__ void __launch_bounds__(128)
head_kernel(const float* __restrict__ fc1_w, const float* __restrict__ fc1_b,
            const float* __restrict__ fc2_w, const float* __restrict__ fc2_b,
            const float* __restrict__ ln_g,  const float* __restrict__ ln_b,
            float* __restrict__ out) {
    extern __shared__ float hs[];
    float* w1 = hs;                  // 128*65
    float* w2 = w1 + 128 * 65;       // 128*129
    float* hv = w2 + 128 * 129;      // HB*64
    float* y1 = hv + HB * 64;        // 128
    float* rs = y1 + 128;            // 4
    float* rq = rs + 4;              // 4
    const int tid = threadIdx.x, b0 = blockIdx.x * HB;

    for (int i = tid; i < 8192;  i += 128) w1[(i >> 6) * 65  + (i & 63)]  = fc1_w[i];
    for (int i = tid; i < 16384; i += 128) w2[(i >> 7) * 129 + (i & 127)] = fc2_w[i];
    for (int i = tid; i < HB * 64; i += 128) hv[i] = g_h2[(size_t)b0 * 64 + i];
    const float b1v = fc1_b[tid], b2v = fc2_b[tid];
    const float gv = ln_g[tid],   bv = ln_b[tid];
    __syncthreads();

    float a2v[HB];
#pragma unroll 1
    for (int bb = 0; bb < HB; bb++) {
        float s0 = b1v, s1 = 0.f;
#pragma unroll
        for (int k = 0; k < 64; k += 2) {
            s0 = fmaf(hv[bb * 64 + k],     w1[tid * 65 + k],     s0);
            s1 = fmaf(hv[bb * 64 + k + 1], w1[tid * 65 + k + 1], s1);
        }
        y1[tid] = fmaxf(s0 + s1, 0.0f);
        __syncthreads();
        float t0 = b2v, t1 = 0.f;
#pragma unroll
        for (int k = 0; k < 128; k += 2) {
            t0 = fmaf(y1[k],     w2[tid * 129 + k],     t0);
            t1 = fmaf(y1[k + 1], w2[tid * 129 + k + 1], t1);
        }
        a2v[bb] = t0 + t1;
        __syncthreads();
    }
#pragma unroll 1
    for (int bb = 0; bb < HB; bb++) {
        float sv = a2v[bb], sq = a2v[bb] * a2v[bb];
#pragma unroll
        for (int o = 16; o > 0; o >>= 1) {
            sv += __shfl_xor_sync(0xffffffffu, sv, o);
            sq += __shfl_xor_sync(0xffffffffu, sq, o);
        }
        if ((tid & 31) == 0) { rs[tid >> 5] = sv; rq[tid >> 5] = sq; }
        __syncthreads();
        float S = rs[0] + rs[1] + rs[2] + rs[3];
        float Q = rq[0] + rq[1] + rq[2] + rq[3];
        float mu  = S * (1.0f / 128.0f);
        float var = Q * (1.0f / 128.0f) - mu * mu;
        out[(size_t)(b0 + bb) * 128 + tid] =
            (a2v[bb] - mu) * rsqrtf(var + 1e-5f) * gv + bv;
        __syncthreads();
    }
}

extern "C" void kernel_launch(void* const* d_in, const int* in_sizes, int n_in,
                              void* d_out, int out_size) {
    const float* x     = (const float*)d_in[0];
    const float* w_ih1 = (const float*)d_in[1];
    const float* w_hh1 = (const float*)d_in[2];
    const float* b_ih1 = (const float*)d_in[3];
    const float* b_hh1 = (const float*)d_in[4];
    const float* w_ih2 = (const float*)d_in[5];
    const float* w_hh2 = (const float*)d_in[6];
    const float* b_ih2 = (const float*)d_in[7];
    const float* b_hh2 = (const float*)d_in[8];
    const float* fc1_w = (const float*)d_in[9];
    const float* fc1_b = (const float*)d_in[10];
    const float* fc2_w = (const float*)d_in[11];
    const float* fc2_b = (const float*)d_in[12];
    const float* ln_g  = (const float*)d_in[13];
    const float* ln_b  = (const float*)d_in[14];
    float* out = (float*)d_out;

    xconv_kernel<<<32768, 256>>>(x);
    lstm_kernel<<<CTAS, TPB>>>(w_ih1, w_hh1, b_ih1, b_hh1,
                               w_ih2, w_hh2, b_ih2, b_hh2);

    int head_smem = (128 * 65 + 128 * 129 + HB * 64 + 128 + 8) * (int)sizeof(float);
    cudaFuncSetAttribute(head_kernel,
                         cudaFuncAttributeMaxDynamicSharedMemorySize, head_smem);
    head_kernel<<<512 / HB, 128, head_smem>>>(fc1_w, fc1_b, fc2_w, fc2_b,
                                              ln_g, ln_b, out);
}

// round 10
// speedup vs baseline: 5.0039x; 1.0530x over previous
#include <cuda_runtime.h>
#include <cuda_fp16.h>
#include <cstdint>

// R10: R8 structure (proven) + split accumulator chains + coalesced xconv
// + cp.async-staged head. Group A (warps 0-7): layer2. Group B: layer1.

#define CTAS  64
#define TPB   512
#define T_LEN 1024

static __device__ float    g_h2[512 * 64];
static __device__ uint32_t g_xh[64 * 1024 * 128];   // [gb][t][word] fp16 pairs

__device__ __forceinline__ uint32_t pkh(float a, float b) {
    __half ha = __float2half_rn(a), hb = __float2half_rn(b);
    return (uint32_t)__half_as_ushort(ha) | ((uint32_t)__half_as_ushort(hb) << 16);
}
__device__ __forceinline__ float tanhax(float x) {
    float y; asm("tanh.approx.f32 %0,%1;" : "=f"(y) : "f"(x)); return y;
}
__device__ __forceinline__ uint32_t cvt2h(float hi, float lo) {
    uint32_t r; asm("cvt.rn.f16x2.f32 %0,%1,%2;" : "=r"(r) : "f"(hi), "f"(lo)); return r;
}
__device__ __forceinline__ uint32_t tanh2(uint32_t v) {
    uint32_t r; asm("tanh.approx.f16x2 %0,%1;" : "=r"(r) : "r"(v)); return r;
}
__device__ __forceinline__ uint32_t tanh2_from(float lo, float hi) {
    return tanh2(cvt2h(hi, lo));
}
__device__ __forceinline__ uint32_t sig2_from(float lo, float hi) {
    uint32_t t = tanh2(cvt2h(0.5f * hi, 0.5f * lo));
    uint32_t r;
    asm("fma.rn.f16x2 %0,%1,%2,%3;" : "=r"(r)
        : "r"(t), "r"(0x38003800u), "r"(0x38003800u));
    return r;
}
__device__ __forceinline__ void mma16(float* d, const uint32_t* a, uint32_t b0, uint32_t b1) {
    asm volatile(
        "mma.sync.aligned.m16n8k16.row.col.f32.f16.f16.f32 "
        "{%0,%1,%2,%3},{%4,%5,%6,%7},{%8,%9},{%0,%1,%2,%3};"
        : "+f"(d[0]), "+f"(d[1]), "+f"(d[2]), "+f"(d[3])
        : "r"(a[0]), "r"(a[1]), "r"(a[2]), "r"(a[3]), "r"(b0), "r"(b1));
}
__device__ __forceinline__ void cpa16(uint32_t d, const void* s) {
    asm volatile("cp.async.ca.shared.global [%0],[%1],16;" :: "r"(d), "l"(s));
}
__device__ __forceinline__ void cpa4(uint32_t d, const void* s) {
    asm volatile("cp.async.ca.shared.global [%0],[%1],4;" :: "r"(d), "l"(s));
}
__device__ __forceinline__ uint32_t s2u(const void* p) {
    uint32_t a;
    asm("{.reg .u64 t; cvta.to.shared.u64 t,%1; cvt.u32.u64 %0,t;}" : "=r"(a) : "l"(p));
    return a;
}

// ---- x pre-conversion (coalesced reads: lane = m fastest) ----
__global__ void __launch_bounds__(256)
xconv_kernel(const float* __restrict__ x) {
    int id = blockIdx.x * 256 + threadIdx.x;
    int m = id & 15, n = (id >> 4) & 7, t = (id >> 7) & 1023, gb = id >> 17;
    const float2 v = *(const float2*)&x[(((size_t)(gb * 8 + n)) * 1024 + t) * 32 + 2 * m];
    g_xh[((size_t)gb << 17) + t * 128 + m * 8 + n] = pkh(v.x, v.y);
}

__global__ void __launch_bounds__(TPB, 1)
lstm_kernel(const float* __restrict__ w_ih1, const float* __restrict__ w_hh1,
            const float* __restrict__ b_ih1, const float* __restrict__ b_hh1,
            const float* __restrict__ w_ih2, const float* __restrict__ w_hh2,
            const float* __restrict__ b_ih2, const float* __restrict__ b_hh2) {
    __shared__ uint32_t h1d[2][256];
    __shared__ uint32_t h2v[256];
    __shared__ uint32_t xv[8][128];
    __shared__ uint32_t ga2h[1024];
    __shared__ uint32_t ga1h[1024];

    const int tid = threadIdx.x;
    const int w   = tid >> 5, L = tid & 31;
    const int wg  = w & 7;
    const int gr  = L >> 2, q = L & 3;
    const int r1  = 32 * wg + gr, r2 = r1 + 8, r3 = r1 + 16, r4 = r1 + 24;
    const int bo  = 8 * q + gr;
    const bool isA = (w < 8);
    const bool tg  = ((wg >> 1) == 2);
    const int tl  = isA ? tid : tid - 256;
    const int uu  = tl & 63, j = tl >> 6;

    uint32_t WF[16][4];
    float bb1, bb2, bb3, bb4;
#define W2AT(r, k) ((k) < 64 ? w_ih2[(r) * 64 + (k)] : w_hh2[(r) * 64 + (k) - 64])
#define W1AT(r, k) ((k) < 64 ? w_hh1[(r) * 64 + (k)] : w_ih1[(r) * 32 + (k) - 64])
    if (isA) {
#pragma unroll
        for (int c = 0; c < 8; c++) {
            int k0 = 16 * c + 2 * q;
            WF[c][0] = pkh(W2AT(r1, k0),     W2AT(r1, k0 + 1));
            WF[c][1] = pkh(W2AT(r2, k0),     W2AT(r2, k0 + 1));
            WF[c][2] = pkh(W2AT(r1, k0 + 8), W2AT(r1, k0 + 9));
            WF[c][3] = pkh(W2AT(r2, k0 + 8), W2AT(r2, k0 + 9));
            WF[8 + c][0] = pkh(W2AT(r3, k0),     W2AT(r3, k0 + 1));
            WF[8 + c][1] = pkh(W2AT(r4, k0),     W2AT(r4, k0 + 1));
            WF[8 + c][2] = pkh(W2AT(r3, k0 + 8), W2AT(r3, k0 + 9));
            WF[8 + c][3] = pkh(W2AT(r4, k0 + 8), W2AT(r4, k0 + 9));
        }
        bb1 = b_ih2[r1] + b_hh2[r1]; bb2 = b_ih2[r2] + b_hh2[r2];
        bb3 = b_ih2[r3] + b_hh2[r3]; bb4 = b_ih2[r4] + b_hh2[r4];
    } else {
#pragma unroll
        for (int c = 0; c < 6; c++) {
            int k0 = 16 * c + 2 * q;
            WF[c][0] = pkh(W1AT(r1, k0),     W1AT(r1, k0 + 1));
            WF[c][1] = pkh(W1AT(r2, k0),     W1AT(r2, k0 + 1));
            WF[c][2] = pkh(W1AT(r1, k0 + 8), W1AT(r1, k0 + 9));
            WF[c][3] = pkh(W1AT(r2, k0 + 8), W1AT(r2, k0 + 9));
            WF[8 + c][0] = pkh(W1AT(r3, k0),     W1AT(r3, k0 + 1));
            WF[8 + c][1] = pkh(W1AT(r4, k0),     W1AT(r4, k0 + 1));
            WF[8 + c][2] = pkh(W1AT(r3, k0 + 8), W1AT(r3, k0 + 9));
            WF[8 + c][3] = pkh(W1AT(r4, k0 + 8), W1AT(r4, k0 + 9));
        }
        bb1 = b_ih1[r1] + b_hh1[r1]; bb2 = b_ih1[r2] + b_hh1[r2];
        bb3 = b_ih1[r3] + b_hh1[r3]; bb4 = b_ih1[r4] + b_hh1[r4];
    }

    if (tid < 256) { h1d[0][tid] = 0; h1d[1][tid] = 0; h2v[tid] = 0; }

    const size_t xg = (size_t)blockIdx.x * 1024 * 128;
    const uint32_t xvb = s2u(xv);
    if (w == 8) {
#pragma unroll
        for (int s = 0; s < 8; s++) {
            cpa16(xvb + (uint32_t)((s * 128 + L * 4) * 4), &g_xh[xg + s * 128 + L * 4]);
            asm volatile("cp.async.commit_group;");
        }
        asm volatile("cp.async.wait_group 0;");
    }
    __syncthreads();

    float cx = 0.0f, cy = 0.0f;

#define ACT_STORE(ga, v0, v1, v2_, v3, rA, rB, bA, bB) do {                    \
        if (tg) { (ga)[q * 256 + (rA)] = tanh2_from((v0) + (bA), (v1) + (bA)); \
                  (ga)[q * 256 + (rB)] = tanh2_from((v2_) + (bB), (v3) + (bB)); } \
        else    { (ga)[q * 256 + (rA)] = sig2_from((v0) + (bA), (v1) + (bA));  \
                  (ga)[q * 256 + (rB)] = sig2_from((v2_) + (bB), (v3) + (bB)); } } while (0)

#define UPDATE(ga, harr) do {                                                  \
        uint32_t wi = (ga)[j * 256 + uu],        wf = (ga)[j * 256 + 64 + uu]; \
        uint32_t wg_ = (ga)[j * 256 + 128 + uu], wo = (ga)[j * 256 + 192 + uu];\
        float2 fi = __half22float2(*(__half2*)&wi);                            \
        float2 ff = __half22float2(*(__half2*)&wf);                            \
        float2 fg = __half22float2(*(__half2*)&wg_);                           \
        float2 fo = __half22float2(*(__half2*)&wo);                            \
        cx = fmaf(ff.x, cx, fi.x * fg.x);                                      \
        cy = fmaf(ff.y, cy, fi.y * fg.y);                                      \
        hx = fo.x * tanhax(cx); hy = fo.y * tanhax(cy);                        \
        __half* hp = (__half*)(harr);                                          \
        hp[(((uu >> 1) * 8 + 2 * j) << 1)     | (uu & 1)] = __float2half_rn(hx);\
        hp[(((uu >> 1) * 8 + 2 * j + 1) << 1) | (uu & 1)] = __float2half_rn(hy);\
    } while (0)

    // ---- prologue: B computes g1(0) (h1(-1)=0 via zeroed h1d[1]) ----
    if (!isA) {
        float dA[4] = {0,0,0,0}, dA2[4] = {0,0,0,0};
        float dB[4] = {0,0,0,0}, dB2[4] = {0,0,0,0};
        const uint32_t* h1c = h1d[1];
#pragma unroll
        for (int c = 0; c < 4; c++) {
            uint32_t b0w = h1c[c * 64 + bo], b1w = h1c[c * 64 + bo + 32];
            mma16(dA, WF[c], b0w, b1w); mma16(dB, WF[8 + c], b0w, b1w);
        }
#pragma unroll
        for (int c = 0; c < 2; c++) {
            uint32_t b0w = xv[0][c * 64 + bo], b1w = xv[0][c * 64 + bo + 32];
            mma16(dA2, WF[4 + c], b0w, b1w); mma16(dB2, WF[12 + c], b0w, b1w);
        }
        ACT_STORE(ga1h, dA[0]+dA2[0], dA[1]+dA2[1], dA[2]+dA2[2], dA[3]+dA2[3],
                  r1, r2, bb1, bb2);
        ACT_STORE(ga1h, dB[0]+dB2[0], dB[1]+dB2[1], dB[2]+dB2[2], dB[3]+dB2[3],
                  r3, r4, bb3, bb4);
        asm volatile("bar.sync 2, 256;" ::: "memory");
        float hx, hy;
        UPDATE(ga1h, h1d[0]);
    }
    __syncthreads();

    // =================== main loop ===================
    for (int t = 0; t < T_LEN; t++) {
        if (isA) {
            // gates2(t): h1(t) + h2(t-1), split chains
            float dA[4] = {0,0,0,0}, dA2[4] = {0,0,0,0};
            float dB[4] = {0,0,0,0}, dB2[4] = {0,0,0,0};
            const uint32_t* h1c = h1d[t & 1];
#pragma unroll
            for (int c = 0; c < 4; c++) {
                uint32_t b0w = h1c[c * 64 + bo], b1w = h1c[c * 64 + bo + 32];
                mma16(dA, WF[c], b0w, b1w); mma16(dB, WF[8 + c], b0w, b1w);
            }
#pragma unroll
            for (int c = 0; c < 4; c++) {
                uint32_t b0w = h2v[c * 64 + bo], b1w = h2v[c * 64 + bo + 32];
                mma16(dA2, WF[4 + c], b0w, b1w); mma16(dB2, WF[12 + c], b0w, b1w);
            }
            ACT_STORE(ga2h, dA[0]+dA2[0], dA[1]+dA2[1], dA[2]+dA2[2], dA[3]+dA2[3],
                      r1, r2, bb1, bb2);
            ACT_STORE(ga2h, dB[0]+dB2[0], dB[1]+dB2[1], dB[2]+dB2[2], dB[3]+dB2[3],
                      r3, r4, bb3, bb4);
            asm volatile("bar.sync 1, 256;" ::: "memory");
            float hx, hy;
            UPDATE(ga2h, h2v);
            if (t == T_LEN - 1) {
                g_h2[(size_t)(blockIdx.x * 8 + 2 * j) * 64 + uu]     = hx;
                g_h2[(size_t)(blockIdx.x * 8 + 2 * j + 1) * 64 + uu] = hy;
            }
        } else {
            if (w == 8) {
                int st = t + 8; if (st > 1023) st = 1023;
                cpa16(xvb + (uint32_t)((((st & 7) * 128) + L * 4) * 4),
                      &g_xh[xg + (size_t)st * 128 + L * 4]);
                asm volatile("cp.async.commit_group;");
            }
            // gates1(t+1): h1(t) + x(t+1), split chains
            float dA[4] = {0,0,0,0}, dA2[4] = {0,0,0,0};
            float dB[4] = {0,0,0,0}, dB2[4] = {0,0,0,0};
            const uint32_t* h1c = h1d[t & 1];
            const uint32_t* xs  = xv[(t + 1) & 7];
#pragma unroll
            for (int c = 0; c < 4; c++) {
                uint32_t b0w = h1c[c * 64 + bo], b1w = h1c[c * 64 + bo + 32];
                mma16(dA, WF[c], b0w, b1w); mma16(dB, WF[8 + c], b0w, b1w);
            }
#pragma unroll
            for (int c = 0; c < 2; c++) {
                uint32_t b0w = xs[c * 64 + bo], b1w = xs[c * 64 + bo + 32];
                mma16(dA2, WF[4 + c], b0w, b1w); mma16(dB2, WF[12 + c], b0w, b1w);
            }
            ACT_STORE(ga1h, dA[0]+dA2[0], dA[1]+dA2[1], dA[2]+dA2[2], dA[3]+dA2[3],
                      r1, r2, bb1, bb2);
            ACT_STORE(ga1h, dB[0]+dB2[0], dB[1]+dB2[1], dB[2]+dB2[2], dB[3]+dB2[3],
                      r3, r4, bb3, bb4);
            asm volatile("bar.sync 2, 256;" ::: "memory");
            float hx, hy;
            UPDATE(ga1h, h1d[(t + 1) & 1]);   // garbage at t=1023, never read
            if (w == 8) asm volatile("cp.async.wait_group 6;");
        }
        __syncthreads();
    }
#undef ACT_STORE
#undef UPDATE
}

// ---------------- head: LN(relu(h@fc1^T+b1)@fc2^T+b2) ----------------
#define HB 8
__global__ void __launch_bounds__(128)
head_kernel(const float* __restrict__ fc1_w, const float* __restrict__ fc1_b,
            const float* __restrict__ fc2_w, const float* __restrict__ fc2_b,
            const float* __restrict__ ln_g,  const float* __restrict__ ln_b,
            float* __restrict__ out) {
    extern __shared__ float hs[];
    float* w1 = hs;                  // 128*65
    float* w2 = w1 + 128 * 65;       // 128*129
    float* hv = w2 + 128 * 129;      // HB*64
    float* y1 = hv + HB * 64;        // 128
    float* rs = y1 + 128;            // 4
    float* rq = rs + 4;              // 4
    const int tid = threadIdx.x, b0 = blockIdx.x * HB;

    for (int i = tid; i < 8192;  i += 128)
        cpa4(s2u(&w1[(i >> 6) * 65 + (i & 63)]), &fc1_w[i]);
    for (int i = tid; i < 16384; i += 128)
        cpa4(s2u(&w2[(i >> 7) * 129 + (i & 127)]), &fc2_w[i]);
    cpa16(s2u(&hv[tid * 4]), &g_h2[(size_t)b0 * 64 + tid * 4]);
    asm volatile("cp.async.commit_group;");
    asm volatile("cp.async.wait_group 0;");
    const float b1v = fc1_b[tid], b2v = fc2_b[tid];
    const float gv = ln_g[tid],   bv = ln_b[tid];
    __syncthreads();

    float a2v[HB];
#pragma unroll 1
    for (int bb = 0; bb < HB; bb++) {
        float s0 = b1v, s1 = 0.f;
#pragma unroll
        for (int k = 0; k < 64; k += 2) {
            s0 = fmaf(hv[bb * 64 + k],     w1[tid * 65 + k],     s0);
            s1 = fmaf(hv[bb * 64 + k + 1], w1[tid * 65 + k + 1], s1);
        }
        y1[tid] = fmaxf(s0 + s1, 0.0f);
        __syncthreads();
        float t0 = b2v, t1 = 0.f;
#pragma unroll
        for (int k = 0; k < 128; k += 2) {
            t0 = fmaf(y1[k],     w2[tid * 129 + k],     t0);
            t1 = fmaf(y1[k + 1], w2[tid * 129 + k + 1], t1);
        }
        a2v[bb] = t0 + t1;
        __syncthreads();
    }
#pragma unroll 1
    for (int bb = 0; bb < HB; bb++) {
        float sv = a2v[bb], sq = a2v[bb] * a2v[bb];
#pragma unroll
        for (int o = 16; o > 0; o >>= 1) {
            sv += __shfl_xor_sync(0xffffffffu, sv, o);
            sq += __shfl_xor_sync(0xffffffffu, sq, o);
        }
        if ((tid & 31) == 0) { rs[tid >> 5] = sv; rq[tid >> 5] = sq; }
        __syncthreads();
        float S = rs[0] + rs[1] + rs[2] + rs[3];
        float Q = rq[0] + rq[1] + rq[2] + rq[3];
        float mu  = S * (1.0f / 128.0f);
        float var = Q * (1.0f / 128.0f) - mu * mu;
        out[(size_t)(b0 + bb) * 128 + tid] =
            (a2v[bb] - mu) * rsqrtf(var + 1e-5f) * gv + bv;
        __syncthreads();
    }
}

extern "C" void kernel_launch(void* const* d_in, const int* in_sizes, int n_in,
                              void* d_out, int out_size) {
    const float* x     = (const float*)d_in[0];
    const float* w_ih1 = (const float*)d_in[1];
    const float* w_hh1 = (const float*)d_in[2];
    const float* b_ih1 = (const float*)d_in[3];
    const float* b_hh1 = (const float*)d_in[4];
    const float* w_ih2 = (const float*)d_in[5];
    const float* w_hh2 = (const float*)d_in[6];
    const float* b_ih2 = (const float*)d_in[7];
    const float* b_hh2 = (const float*)d_in[8];
    const float* fc1_w = (const float*)d_in[9];
    const float* fc1_b = (const float*)d_in[10];
    const float* fc2_w = (const float*)d_in[11];
    const float* fc2_b = (const float*)d_in[12];
    const float* ln_g  = (const float*)d_in[13];
    const float* ln_b  = (const float*)d_in[14];
    float* out = (float*)d_out;

    xconv_kernel<<<32768, 256>>>(x);
    lstm_kernel<<<CTAS, TPB>>>(w_ih1, w_hh1, b_ih1, b_hh1,
                               w_ih2, w_hh2, b_ih2, b_hh2);

    int head_smem = (128 * 65 + 128 * 129 + HB * 64 + 128 + 8) * (int)sizeof(float);
    cudaFuncSetAttribute(head_kernel,
                         cudaFuncAttributeMaxDynamicSharedMemorySize, head_smem);
    head_kernel<<<512 / HB, 128, head_smem>>>(fc1_w, fc1_b, fc2_w, fc2_b,
                                              ln_g, ln_b, out);
}

// round 13
// speedup vs baseline: 5.2590x; 1.0510x over previous
#include <cuda_runtime.h>
#include <cuda_fp16.h>
#include <cstdint>

// R13: R10 (proven 624.7us) + in-kernel x staging (xconv kernel deleted).
// Group A (warps 0-7): layer2. Group B (warps 8-15): layer1.
// Warp 8 cp.asyncs fp32 x into xf ring; warps 8-11 convert slot t+2 -> xv.

#define CTAS  64
#define TPB   512
#define T_LEN 1024

static __device__ float g_h2[512 * 64];

__device__ __forceinline__ uint32_t pkh(float a, float b) {
    __half ha = __float2half_rn(a), hb = __float2half_rn(b);
    return (uint32_t)__half_as_ushort(ha) | ((uint32_t)__half_as_ushort(hb) << 16);
}
__device__ __forceinline__ float tanhax(float x) {
    float y; asm("tanh.approx.f32 %0,%1;" : "=f"(y) : "f"(x)); return y;
}
__device__ __forceinline__ uint32_t cvt2h(float hi, float lo) {
    uint32_t r; asm("cvt.rn.f16x2.f32 %0,%1,%2;" : "=r"(r) : "f"(hi), "f"(lo)); return r;
}
__device__ __forceinline__ uint32_t tanh2(uint32_t v) {
    uint32_t r; asm("tanh.approx.f16x2 %0,%1;" : "=r"(r) : "r"(v)); return r;
}
__device__ __forceinline__ uint32_t tanh2_from(float lo, float hi) {
    return tanh2(cvt2h(hi, lo));
}
__device__ __forceinline__ uint32_t sig2_from(float lo, float hi) {
    uint32_t t = tanh2(cvt2h(0.5f * hi, 0.5f * lo));
    uint32_t r;
    asm("fma.rn.f16x2 %0,%1,%2,%3;" : "=r"(r)
        : "r"(t), "r"(0x38003800u), "r"(0x38003800u));
    return r;
}
__device__ __forceinline__ void mma16(float* d, const uint32_t* a, uint32_t b0, uint32_t b1) {
    asm volatile(
        "mma.sync.aligned.m16n8k16.row.col.f32.f16.f16.f32 "
        "{%0,%1,%2,%3},{%4,%5,%6,%7},{%8,%9},{%0,%1,%2,%3};"
        : "+f"(d[0]), "+f"(d[1]), "+f"(d[2]), "+f"(d[3])
        : "r"(a[0]), "r"(a[1]), "r"(a[2]), "r"(a[3]), "r"(b0), "r"(b1));
}
__device__ __forceinline__ void cpa16(uint32_t d, const void* s) {
    asm volatile("cp.async.ca.shared.global [%0],[%1],16;" :: "r"(d), "l"(s));
}
__device__ __forceinline__ void cpa4(uint32_t d, const void* s) {
    asm volatile("cp.async.ca.shared.global [%0],[%1],4;" :: "r"(d), "l"(s));
}
__device__ __forceinline__ uint32_t s2u(const void* p) {
    uint32_t a;
    asm("{.reg .u64 t; cvta.to.shared.u64 t,%1; cvt.u32.u64 %0,t;}" : "=r"(a) : "l"(p));
    return a;
}

__global__ void __launch_bounds__(TPB, 1)
lstm_kernel(const float* __restrict__ x,
            const float* __restrict__ w_ih1, const float* __restrict__ w_hh1,
            const float* __restrict__ b_ih1, const float* __restrict__ b_hh1,
            const float* __restrict__ w_ih2, const float* __restrict__ w_hh2,
            const float* __restrict__ b_ih2, const float* __restrict__ b_hh2) {
    __shared__ uint32_t h1d[2][256];
    __shared__ uint32_t h2v[256];
    __shared__ uint32_t xv[8][128];     // fp16-pair words [m*8+b]
    __shared__ float    xf[8][256];     // fp32 staging ring [b*32+k]
    __shared__ uint32_t ga2h[1024];
    __shared__ uint32_t ga1h[1024];

    const int tid = threadIdx.x;
    const int w   = tid >> 5, L = tid & 31;
    const int wg  = w & 7;
    const int gr  = L >> 2, q = L & 3;
    const int r1  = 32 * wg + gr, r2 = r1 + 8, r3 = r1 + 16, r4 = r1 + 24;
    const int bo  = 8 * q + gr;
    const bool isA = (w < 8);
    const bool tg  = ((wg >> 1) == 2);
    const int tl  = isA ? tid : tid - 256;
    const int uu  = tl & 63, j = tl >> 6;

    uint32_t WF[16][4];
    float bb1, bb2, bb3, bb4;
#define W2AT(r, k) ((k) < 64 ? w_ih2[(r) * 64 + (k)] : w_hh2[(r) * 64 + (k) - 64])
#define W1AT(r, k) ((k) < 64 ? w_hh1[(r) * 64 + (k)] : w_ih1[(r) * 32 + (k) - 64])
    if (isA) {
#pragma unroll
        for (int c = 0; c < 8; c++) {
            int k0 = 16 * c + 2 * q;
            WF[c][0] = pkh(W2AT(r1, k0),     W2AT(r1, k0 + 1));
            WF[c][1] = pkh(W2AT(r2, k0),     W2AT(r2, k0 + 1));
            WF[c][2] = pkh(W2AT(r1, k0 + 8), W2AT(r1, k0 + 9));
            WF[c][3] = pkh(W2AT(r2, k0 + 8), W2AT(r2, k0 + 9));
            WF[8 + c][0] = pkh(W2AT(r3, k0),     W2AT(r3, k0 + 1));
            WF[8 + c][1] = pkh(W2AT(r4, k0),     W2AT(r4, k0 + 1));
            WF[8 + c][2] = pkh(W2AT(r3, k0 + 8), W2AT(r3, k0 + 9));
            WF[8 + c][3] = pkh(W2AT(r4, k0 + 8), W2AT(r4, k0 + 9));
        }
        bb1 = b_ih2[r1] + b_hh2[r1]; bb2 = b_ih2[r2] + b_hh2[r2];
        bb3 = b_ih2[r3] + b_hh2[r3]; bb4 = b_ih2[r4] + b_hh2[r4];
    } else {
#pragma unroll
        for (int c = 0; c < 6; c++) {
            int k0 = 16 * c + 2 * q;
            WF[c][0] = pkh(W1AT(r1, k0),     W1AT(r1, k0 + 1));
            WF[c][1] = pkh(W1AT(r2, k0),     W1AT(r2, k0 + 1));
            WF[c][2] = pkh(W1AT(r1, k0 + 8), W1AT(r1, k0 + 9));
            WF[c][3] = pkh(W1AT(r2, k0 + 8), W1AT(r2, k0 + 9));
            WF[8 + c][0] = pkh(W1AT(r3, k0),     W1AT(r3, k0 + 1));
            WF[8 + c][1] = pkh(W1AT(r4, k0),     W1AT(r4, k0 + 1));
            WF[8 + c][2] = pkh(W1AT(r3, k0 + 8), W1AT(r3, k0 + 9));
            WF[8 + c][3] = pkh(W1AT(r4, k0 + 8), W1AT(r4, k0 + 9));
        }
        bb1 = b_ih1[r1] + b_hh1[r1]; bb2 = b_ih1[r2] + b_hh1[r2];
        bb3 = b_ih1[r3] + b_hh1[r3]; bb4 = b_ih1[r4] + b_hh1[r4];
    }

    if (tid < 256) { h1d[0][tid] = 0; h1d[1][tid] = 0; h2v[tid] = 0; }

    // ---- in-kernel x staging: warp 8 cp.asyncs fp32 rows into xf ring ----
    const float* xb = x + (size_t)blockIdx.x * 8 * 1024 * 32;
    const uint32_t xfb = s2u(xf);
#define STG(t_) do { int st = (t_) > 1023 ? 1023 : (t_);                          \
        const float* _s = xb + ((size_t)(L >> 2) * 1024 + st) * 32 + (L & 3) * 8; \
        uint32_t _d = xfb + (uint32_t)((((st) & 7) * 256 + (L >> 2) * 32 + (L & 3) * 8) * 4); \
        cpa16(_d, _s); cpa16(_d + 16, _s + 4);                                    \
        asm volatile("cp.async.commit_group;"); } while (0)
#define XCONV(tn) do { int m = tl & 15, bb = tl >> 4;                             \
        const float2 v = *(const float2*)&xf[(tn) & 7][bb * 32 + 2 * m];          \
        xv[(tn) & 7][m * 8 + bb] = pkh(v.x, v.y); } while (0)

    if (w == 8) {
#pragma unroll
        for (int s = 0; s < 8; s++) STG(s);
        asm volatile("cp.async.wait_group 0;");
    }
    __syncthreads();
    if (!isA && tl < 128) { XCONV(0); XCONV(1); }
    __syncthreads();

    float cx = 0.0f, cy = 0.0f;

#define ACT_STORE(ga, v0, v1, v2_, v3, rA, rB, bA, bB) do {                    \
        if (tg) { (ga)[q * 256 + (rA)] = tanh2_from((v0) + (bA), (v1) + (bA)); \
                  (ga)[q * 256 + (rB)] = tanh2_from((v2_) + (bB), (v3) + (bB)); } \
        else    { (ga)[q * 256 + (rA)] = sig2_from((v0) + (bA), (v1) + (bA));  \
                  (ga)[q * 256 + (rB)] = sig2_from((v2_) + (bB), (v3) + (bB)); } } while (0)

#define UPDATE(ga, harr) do {                                                  \
        uint32_t wi = (ga)[j * 256 + uu],        wf = (ga)[j * 256 + 64 + uu]; \
        uint32_t wg_ = (ga)[j * 256 + 128 + uu], wo = (ga)[j * 256 + 192 + uu];\
        float2 fi = __half22float2(*(__half2*)&wi);                            \
        float2 ff = __half22float2(*(__half2*)&wf);                            \
        float2 fg = __half22float2(*(__half2*)&wg_);                           \
        float2 fo = __half22float2(*(__half2*)&wo);                            \
        cx = fmaf(ff.x, cx, fi.x * fg.x);                                      \
        cy = fmaf(ff.y, cy, fi.y * fg.y);                                      \
        hx = fo.x * tanhax(cx); hy = fo.y * tanhax(cy);                        \
        __half* hp = (__half*)(harr);                                          \
        hp[(((uu >> 1) * 8 + 2 * j) << 1)     | (uu & 1)] = __float2half_rn(hx);\
        hp[(((uu >> 1) * 8 + 2 * j + 1) << 1) | (uu & 1)] = __float2half_rn(hy);\
    } while (0)

    // ---- prologue: B computes g1(0) (h1(-1)=0 via zeroed h1d[1]) ----
    if (!isA) {
        float dA[4] = {0,0,0,0}, dA2[4] = {0,0,0,0};
        float dB[4] = {0,0,0,0}, dB2[4] = {0,0,0,0};
        const uint32_t* h1c = h1d[1];
#pragma unroll
        for (int c = 0; c < 4; c++) {
            uint32_t b0w = h1c[c * 64 + bo], b1w = h1c[c * 64 + bo + 32];
            mma16(dA, WF[c], b0w, b1w); mma16(dB, WF[8 + c], b0w, b1w);
        }
#pragma unroll
        for (int c = 0; c < 2; c++) {
            uint32_t b0w = xv[0][c * 64 + bo], b1w = xv[0][c * 64 + bo + 32];
            mma16(dA2, WF[4 + c], b0w, b1w); mma16(dB2, WF[12 + c], b0w, b1w);
        }
        ACT_STORE(ga1h, dA[0]+dA2[0], dA[1]+dA2[1], dA[2]+dA2[2], dA[3]+dA2[3],
                  r1, r2, bb1, bb2);
        ACT_STORE(ga1h, dB[0]+dB2[0], dB[1]+dB2[1], dB[2]+dB2[2], dB[3]+dB2[3],
                  r3, r4, bb3, bb4);
        asm volatile("bar.sync 2, 256;" ::: "memory");
        float hx, hy;
        UPDATE(ga1h, h1d[0]);
    }
    __syncthreads();

    // =================== main loop ===================
    for (int t = 0; t < T_LEN; t++) {
        if (isA) {
            // gates2(t): h1(t) + h2(t-1), split chains
            float dA[4] = {0,0,0,0}, dA2[4] = {0,0,0,0};
            float dB[4] = {0,0,0,0}, dB2[4] = {0,0,0,0};
            const uint32_t* h1c = h1d[t & 1];
#pragma unroll
            for (int c = 0; c < 4; c++) {
                uint32_t b0w = h1c[c * 64 + bo], b1w = h1c[c * 64 + bo + 32];
                mma16(dA, WF[c], b0w, b1w); mma16(dB, WF[8 + c], b0w, b1w);
            }
#pragma unroll
            for (int c = 0; c < 4; c++) {
                uint32_t b0w = h2v[c * 64 + bo], b1w = h2v[c * 64 + bo + 32];
                mma16(dA2, WF[4 + c], b0w, b1w); mma16(dB2, WF[12 + c], b0w, b1w);
            }
            ACT_STORE(ga2h, dA[0]+dA2[0], dA[1]+dA2[1], dA[2]+dA2[2], dA[3]+dA2[3],
                      r1, r2, bb1, bb2);
            ACT_STORE(ga2h, dB[0]+dB2[0], dB[1]+dB2[1], dB[2]+dB2[2], dB[3]+dB2[3],
                      r3, r4, bb3, bb4);
            asm volatile("bar.sync 1, 256;" ::: "memory");
            float hx, hy;
            UPDATE(ga2h, h2v);
            if (t == T_LEN - 1) {
                g_h2[(size_t)(blockIdx.x * 8 + 2 * j) * 64 + uu]     = hx;
                g_h2[(size_t)(blockIdx.x * 8 + 2 * j + 1) * 64 + uu] = hy;
            }
        } else {
            if (w == 8) STG(t + 8);
            if (tl < 128 && t + 2 < T_LEN) XCONV(t + 2);
            // gates1(t+1): h1(t) + x(t+1), split chains
            float dA[4] = {0,0,0,0}, dA2[4] = {0,0,0,0};
            float dB[4] = {0,0,0,0}, dB2[4] = {0,0,0,0};
            const uint32_t* h1c = h1d[t & 1];
            const uint32_t* xs  = xv[(t + 1) & 7];
#pragma unroll
            for (int c = 0; c < 4; c++) {
                uint32_t b0w = h1c[c * 64 + bo], b1w = h1c[c * 64 + bo + 32];
                mma16(dA, WF[c], b0w, b1w); mma16(dB, WF[8 + c], b0w, b1w);
            }
#pragma unroll
            for (int c = 0; c < 2; c++) {
                uint32_t b0w = xs[c * 64 + bo], b1w = xs[c * 64 + bo + 32];
                mma16(dA2, WF[4 + c], b0w, b1w); mma16(dB2, WF[12 + c], b0w, b1w);
            }
            ACT_STORE(ga1h, dA[0]+dA2[0], dA[1]+dA2[1], dA[2]+dA2[2], dA[3]+dA2[3],
                      r1, r2, bb1, bb2);
            ACT_STORE(ga1h, dB[0]+dB2[0], dB[1]+dB2[1], dB[2]+dB2[2], dB[3]+dB2[3],
                      r3, r4, bb3, bb4);
            asm volatile("bar.sync 2, 256;" ::: "memory");
            float hx, hy;
            UPDATE(ga1h, h1d[(t + 1) & 1]);   // garbage at t=1023, never read
            if (w == 8) asm volatile("cp.async.wait_group 4;");
        }
        __syncthreads();
    }
#undef STG
#undef XCONV
#undef ACT_STORE
#undef UPDATE
}

// ---------------- head: LN(relu(h@fc1^T+b1)@fc2^T+b2) ----------------
#define HB 8
__global__ void __launch_bounds__(128)
head_kernel(const float* __restrict__ fc1_w, const float* __restrict__ fc1_b,
            const float* __restrict__ fc2_w, const float* __restrict__ fc2_b,
            const float* __restrict__ ln_g,  const float* __restrict__ ln_b,
            float* __restrict__ out) {
    extern __shared__ float hs[];
    float* w1 = hs;                  // 128*65
    float* w2 = w1 + 128 * 65;       // 128*129
    float* hv = w2 + 128 * 129;      // HB*64
    float* y1 = hv + HB * 64;        // 128
    float* rs = y1 + 128;            // 4
    float* rq = rs + 4;              // 4
    const int tid = threadIdx.x, b0 = blockIdx.x * HB;

    for (int i = tid; i < 8192;  i += 128)
        cpa4(s2u(&w1[(i >> 6) * 65 + (i & 63)]), &fc1_w[i]);
    for (int i = tid; i < 16384; i += 128)
        cpa4(s2u(&w2[(i >> 7) * 129 + (i & 127)]), &fc2_w[i]);
    cpa16(s2u(&hv[tid * 4]), &g_h2[(size_t)b0 * 64 + tid * 4]);
    asm volatile("cp.async.commit_group;");
    asm volatile("cp.async.wait_group 0;");
    const float b1v = fc1_b[tid], b2v = fc2_b[tid];
    const float gv = ln_g[tid],   bv = ln_b[tid];
    __syncthreads();

    float a2v[HB];
#pragma unroll 1
    for (int bb = 0; bb < HB; bb++) {
        float s0 = b1v, s1 = 0.f;
#pragma unroll
        for (int k = 0; k < 64; k += 2) {
            s0 = fmaf(hv[bb * 64 + k],     w1[tid * 65 + k],     s0);
            s1 = fmaf(hv[bb * 64 + k + 1], w1[tid * 65 + k + 1], s1);
        }
        y1[tid] = fmaxf(s0 + s1, 0.0f);
        __syncthreads();
        float t0 = b2v, t1 = 0.f;
#pragma unroll
        for (int k = 0; k < 128; k += 2) {
            t0 = fmaf(y1[k],     w2[tid * 129 + k],     t0);
            t1 = fmaf(y1[k + 1], w2[tid * 129 + k + 1], t1);
        }
        a2v[bb] = t0 + t1;
        __syncthreads();
    }
#pragma unroll 1
    for (int bb = 0; bb < HB; bb++) {
        float sv = a2v[bb], sq = a2v[bb] * a2v[bb];
#pragma unroll
        for (int o = 16; o > 0; o >>= 1) {
            sv += __shfl_xor_sync(0xffffffffu, sv, o);
            sq += __shfl_xor_sync(0xffffffffu, sq, o);
        }
        if ((tid & 31) == 0) { rs[tid >> 5] = sv; rq[tid >> 5] = sq; }
        __syncthreads();
        float S = rs[0] + rs[1] + rs[2] + rs[3];
        float Q = rq[0] + rq[1] + rq[2] + rq[3];
        float mu  = S * (1.0f / 128.0f);
        float var = Q * (1.0f / 128.0f) - mu * mu;
        out[(size_t)(b0 + bb) * 128 + tid] =
            (a2v[bb] - mu) * rsqrtf(var + 1e-5f) * gv + bv;
        __syncthreads();
    }
}

extern "C" void kernel_launch(void* const* d_in, const int* in_sizes, int n_in,
                              void* d_out, int out_size) {
    const float* x     = (const float*)d_in[0];
    const float* w_ih1 = (const float*)d_in[1];
    const float* w_hh1 = (const float*)d_in[2];
    const float* b_ih1 = (const float*)d_in[3];
    const float* b_hh1 = (const float*)d_in[4];
    const float* w_ih2 = (const float*)d_in[5];
    const float* w_hh2 = (const float*)d_in[6];
    const float* b_ih2 = (const float*)d_in[7];
    const float* b_hh2 = (const float*)d_in[8];
    const float* fc1_w = (const float*)d_in[9];
    const float* fc1_b = (const float*)d_in[10];
    const float* fc2_w = (const float*)d_in[11];
    const float* fc2_b = (const float*)d_in[12];
    const float* ln_g  = (const float*)d_in[13];
    const float* ln_b  = (const float*)d_in[14];
    float* out = (float*)d_out;

    lstm_kernel<<<CTAS, TPB>>>(x, w_ih1, w_hh1, b_ih1, b_hh1,
                               w_ih2, w_hh2, b_ih2, b_hh2);

    int head_smem = (128 * 65 + 128 * 129 + HB * 64 + 128 + 8) * (int)sizeof(float);
    cudaFuncSetAttribute(head_kernel,
                         cudaFuncAttributeMaxDynamicSharedMemorySize, head_smem);
    head_kernel<<<512 / HB, 128, head_smem>>>(fc1_w, fc1_b, fc2_w, fc2_b,
                                              ln_g, ln_b, out);
}